// round 13
// baseline (speedup 1.0000x reference)
#include <cuda_runtime.h>
#include <cuda_bf16.h>
#include <stdint.h>
#include <math.h>

#define BN   16
#define DD   768
#define NN   1024
#define ZZ   256
#define TK   512

// int8 quant scales
#define SX   (6.5f/127.0f)
#define SW   (0.135f/127.0f)

// -------- scratch (device globals; no allocation allowed) --------
__device__ float g_score[BN*NN];
__device__ float g_mu[BN*NN];
__device__ float g_rstd[BN*NN];
__device__ int   g_topidx[BN*TK];
__device__ int   g_mask[BN*NN];
__device__ float g_bmin[BN];
__device__ float g_bmax[BN];
__device__ float g_W[DD*ZZ];
__device__ float g_c0[ZZ];
__device__ float g_c1[ZZ];
__device__ float g_wcol[ZZ];
// int8 2-level split operands for k1g
__device__ __align__(16) int8_t g_x1[16384*768];          // x lvl1 [token][d]
__device__ __align__(16) int8_t g_x2[16384*768];          // x lvl2
__device__ __align__(16) int8_t g_wt1[768*768];           // w1^T lvl1 [e][k]
__device__ __align__(16) int8_t g_wt2[768*768];           // w1^T lvl2
// bf16 split operands for k7g
__device__ __align__(16) __nv_bfloat16 g_xh[16384*768];   // x hi  [token][d]
__device__ __align__(16) __nv_bfloat16 g_xl[16384*768];   // x lo
__device__ __align__(16) __nv_bfloat16 g_w2h[256*768];    // W^T hi [o][d]
__device__ __align__(16) __nv_bfloat16 g_w2l[256*768];    // W^T lo
__device__ float g_partial[12*16384];                     // per n-tile token partials

// ---------------- smem / async helpers ----------------
__device__ __forceinline__ uint32_t smem_u32(const void* p) {
    uint32_t a;
    asm("{ .reg .u64 t; cvta.to.shared.u64 t, %1; cvt.u32.u64 %0, t; }" : "=r"(a) : "l"(p));
    return a;
}
#define SMEM_SWZ(off) ((off) ^ (((off) >> 3) & 0x70))
#define CP16(dst, src)   asm volatile("cp.async.cg.shared.global [%0], [%1], 16;" :: "r"(dst), "l"(src))
#define CP_COMMIT()      asm volatile("cp.async.commit_group;" ::: "memory")
#define CP_WAIT0()       asm volatile("cp.async.wait_group 0;" ::: "memory")
#define CP_WAIT1()       asm volatile("cp.async.wait_group 1;" ::: "memory")

#define LDSM4(r, a) \
    asm volatile("ldmatrix.sync.aligned.m8n8.x4.shared.b16 {%0,%1,%2,%3}, [%4];" \
        : "=r"((r)[0]), "=r"((r)[1]), "=r"((r)[2]), "=r"((r)[3]) : "r"(a))

#define MMA16816(d, a, b0, b1) \
    asm volatile("mma.sync.aligned.m16n8k16.row.col.f32.bf16.bf16.f32 " \
        "{%0,%1,%2,%3},{%4,%5,%6,%7},{%8,%9},{%0,%1,%2,%3};" \
        : "+f"((d)[0]), "+f"((d)[1]), "+f"((d)[2]), "+f"((d)[3]) \
        : "r"((a)[0]), "r"((a)[1]), "r"((a)[2]), "r"((a)[3]), "r"(b0), "r"(b1))

// int8 k32 MMA, s32 accumulate (fragments alias the b16 k16 layout bytes)
#define MMAI(d, a, b0, b1) \
    asm volatile("mma.sync.aligned.m16n8k32.row.col.s32.s8.s8.s32 " \
        "{%0,%1,%2,%3},{%4,%5,%6,%7},{%8,%9},{%0,%1,%2,%3};" \
        : "+r"((d)[0]), "+r"((d)[1]), "+r"((d)[2]), "+r"((d)[3]) \
        : "r"((a)[0]), "r"((a)[1]), "r"((a)[2]), "r"((a)[3]), "r"(b0), "r"(b1))

__device__ __forceinline__ void quant2(float v, float inv_s, float s,
                                       int8_t& o1, int8_t& o2) {
    float a = rintf(v * inv_s);
    a = fminf(fmaxf(a, -127.f), 127.f);
    float r = v - a * s;
    float b = rintf(r * inv_s * 254.f);
    b = fminf(fmaxf(b, -127.f), 127.f);
    o1 = (int8_t)a; o2 = (int8_t)b;
}

// =================================================================
// KCW: transpose + 2-level int8 quant of w1 -> g_wt1/g_wt2 [e][k]
// =================================================================
__global__ void kc_convw(const float* __restrict__ w1)
{
    __shared__ float ts[32][33];
    const int tx = threadIdx.x, ty = threadIdx.y;
    const int k0 = blockIdx.x * 32, e0 = blockIdx.y * 32;
    #pragma unroll
    for (int j = 0; j < 32; j += 8)
        ts[ty + j][tx] = w1[(size_t)(k0 + ty + j)*768 + e0 + tx];
    __syncthreads();
    const float invs = 1.0f / SW;
    #pragma unroll
    for (int j = 0; j < 32; j += 8) {
        float v = ts[tx][ty + j];
        size_t o = (size_t)(e0 + ty + j)*768 + k0 + tx;
        int8_t q1, q2;
        quant2(v, invs, SW, q1, q2);
        g_wt1[o] = q1;
        g_wt2[o] = q2;
    }
}

// =================================================================
// KCW2: transpose + bf16 split g_W[d][o] -> g_w2h/g_w2l [o][d]
// =================================================================
__global__ void kc_convw2()
{
    __shared__ float ts[32][33];
    const int tx = threadIdx.x, ty = threadIdx.y;
    const int d0 = blockIdx.x * 32, o0 = blockIdx.y * 32;
    #pragma unroll
    for (int j = 0; j < 32; j += 8)
        ts[ty + j][tx] = g_W[(size_t)(d0 + ty + j)*256 + o0 + tx];
    __syncthreads();
    #pragma unroll
    for (int j = 0; j < 32; j += 8) {
        float v = ts[tx][ty + j];
        size_t o = (size_t)(o0 + ty + j)*768 + d0 + tx;
        __nv_bfloat16 h = __float2bfloat16(v);
        g_w2h[o] = h;
        g_w2l[o] = __float2bfloat16(v - __bfloat162float(h));
    }
}

// =================================================================
// KWCOL: g_wcol[o] = sum_d W[d][o]  (1024 threads, 4 row-chunks)
// =================================================================
__global__ void kwcol()
{
    __shared__ float red[4][256];
    const int o = threadIdx.x & 255, ch = threadIdx.x >> 8;
    float s = 0.f;
    #pragma unroll 8
    for (int d = ch*192; d < (ch+1)*192; ++d) s += g_W[d*256 + o];
    red[ch][o] = s;
    __syncthreads();
    if (ch == 0) g_wcol[o] = red[0][o] + red[1][o] + red[2][o] + red[3][o];
}

// =================================================================
// KCX: transpose x, mu/rstd, emit bf16 hi/lo AND int8 2-level
// =================================================================
__global__ void __launch_bounds__(512, 1)
kc_convx(const float* __restrict__ IF, int blk_base)
{
    extern __shared__ float xs[];          // [d][t] : 768 x 64
    const int tid = threadIdx.x;
    const int ty  = tid >> 5, tx = tid & 31;
    const int blk = blk_base + blockIdx.x;
    const int b   = blk >> 4;
    const int n0  = (blk & 15) << 6;

    const float4* base4 = (const float4*)(IF + (size_t)b * DD * NN);
    const int n04 = n0 >> 2;
    for (int v = tid; v < 64*768/4; v += 512) {
        int d  = v >> 4;
        int t4 = v & 15;
        float4 f = base4[(size_t)d*256 + n04 + t4];
        float2* row = (float2*)(xs + d*64);
        row[t4*2 + 0] = make_float2(f.x, f.y);
        row[t4*2 + 1] = make_float2(f.z, f.w);
    }
    __syncthreads();

    const float2* xs2 = (const float2*)xs;
    for (int i = 0; i < 2; ++i) {
        int tp = ty*2 + i;
        float sx = 0.f, sy = 0.f, ssx = 0.f, ssy = 0.f;
        for (int d = tx; d < 768; d += 32) {
            float2 v = xs2[d*32 + tp];
            sx += v.x; ssx = fmaf(v.x, v.x, ssx);
            sy += v.y; ssy = fmaf(v.y, v.y, ssy);
        }
        for (int off = 16; off; off >>= 1) {
            sx  += __shfl_xor_sync(0xffffffffu, sx,  off);
            sy  += __shfl_xor_sync(0xffffffffu, sy,  off);
            ssx += __shfl_xor_sync(0xffffffffu, ssx, off);
            ssy += __shfl_xor_sync(0xffffffffu, ssy, off);
        }
        if (tx == 0) {
            float mux = sx * (1.0f/768.0f);
            float muy = sy * (1.0f/768.0f);
            g_mu  [b*NN + n0 + 2*tp + 0] = mux;
            g_mu  [b*NN + n0 + 2*tp + 1] = muy;
            g_rstd[b*NN + n0 + 2*tp + 0] = rsqrtf(ssx*(1.0f/768.0f) - mux*mux + 1e-5f);
            g_rstd[b*NN + n0 + 2*tp + 1] = rsqrtf(ssy*(1.0f/768.0f) - muy*muy + 1e-5f);
        }
    }

    const int t  = tid & 63, dq = tid >> 6;
    const int gtok = b*1024 + n0 + t;

    // bf16 hi/lo (for k7g)
    uint4* oh = (uint4*)(g_xh + (size_t)gtok*768);
    uint4* ol = (uint4*)(g_xl + (size_t)gtok*768);
    for (int d8 = dq; d8 < 96; d8 += 8) {
        union { __nv_bfloat16 h[8]; uint4 u; } Uh, Ul;
        #pragma unroll
        for (int i = 0; i < 8; ++i) {
            float v = xs[(d8*8 + i)*64 + t];
            __nv_bfloat16 h = __float2bfloat16(v);
            Uh.h[i] = h;
            Ul.h[i] = __float2bfloat16(v - __bfloat162float(h));
        }
        oh[d8] = Uh.u;
        ol[d8] = Ul.u;
    }

    // int8 2-level (for k1g)
    uint4* o1 = (uint4*)(g_x1 + (size_t)gtok*768);
    uint4* o2 = (uint4*)(g_x2 + (size_t)gtok*768);
    const float invs = 1.0f / SX;
    for (int d16 = dq; d16 < 48; d16 += 8) {
        union { int8_t c[16]; uint4 u; } U1, U2;
        #pragma unroll
        for (int i = 0; i < 16; ++i) {
            float v = xs[(d16*16 + i)*64 + t];
            quant2(v, invs, SX, U1.c[i], U2.c[i]);
        }
        o1[d16] = U1.u;
        o2[d16] = U2.u;
    }
}

// =================================================================
// K1G: IMMA (s8 m16n8k32) Ozaki-split GEMM, 4 products / 3 s32 accs.
// Tile 128 tok x 64 e; 512 threads, 16 warps (4m x 4n), warp 32x16.
// BK = 128 int8 bytes (6 chunks over K=768); 3-stage, 1 barrier/chunk.
// Epilogue: h = C1*A + C2*B + C3*C; partial = sum_e relu(h+b1)*w2.
// =================================================================
__global__ void __launch_bounds__(512, 1)
k1g_gemm(const float* __restrict__ b1, const float* __restrict__ w2, int m_base)
{
    extern __shared__ char dsm[];
    __shared__ float sb1[64];
    __shared__ float sw2[64];
    __shared__ float spart[128];

    const int tid  = threadIdx.x;
    const int wid  = tid >> 5, lane = tid & 31;
    const int mt   = m_base + blockIdx.x / 12;
    const int nt   = blockIdx.x % 12;
    const int m0   = mt * 128;
    const int e0   = nt * 64;
    const int wm   = (wid & 3) * 32;
    const int wn   = (wid >> 2) * 16;

    const uint32_t sbase = (smem_u32(dsm) + 1023u) & ~1023u;

    if (tid < 64) {
        sb1[tid] = b1[e0 + tid];
        sw2[tid] = w2[e0 + tid];
    }
    if (tid < 128) spart[tid] = 0.f;

    const char* x1 = (const char*)g_x1;
    const char* x2 = (const char*)g_x2;
    const char* w1q = (const char*)g_wt1;
    const char* w2q = (const char*)g_wt2;

    // stage: A lvl0 16K | A lvl1 16K | B lvl0 8K | B lvl1 8K = 48K
    auto load_chunk = [&](int c, int st) {
        const uint32_t sA = sbase + (uint32_t)st * 49152u;
        const int kb = c * 128;
        #pragma unroll
        for (int q = 0; q < 4; ++q) {          // A: 2048 segs
            int idx  = tid + q*512;
            int lvl = idx >> 10, rem = idx & 1023;
            int r = rem >> 3, ci = rem & 7;
            uint32_t off = (uint32_t)(r*128 + ci*16);
            uint32_t dst = sA + (uint32_t)lvl*16384u + SMEM_SWZ(off);
            const char* src = (lvl ? x2 : x1) + (size_t)(m0 + r)*768 + kb + ci*16;
            CP16(dst, src);
        }
        #pragma unroll
        for (int q = 0; q < 2; ++q) {          // B: 1024 segs
            int idx  = tid + q*512;
            int lvl = idx >> 9, rem = idx & 511;
            int r = rem >> 3, ci = rem & 7;
            uint32_t off = (uint32_t)(r*128 + ci*16);
            uint32_t dst = sA + 32768u + (uint32_t)lvl*8192u + SMEM_SWZ(off);
            const char* src = (lvl ? w2q : w1q) + (size_t)(e0 + r)*768 + kb + ci*16;
            CP16(dst, src);
        }
        CP_COMMIT();
    };

    int accA[2][2][4], accB[2][2][4], accC[2][2][4];
    #pragma unroll
    for (int i = 0; i < 2; ++i)
        #pragma unroll
        for (int j = 0; j < 2; ++j)
            #pragma unroll
            for (int q = 0; q < 4; ++q) {
                accA[i][j][q] = 0; accB[i][j][q] = 0; accC[i][j][q] = 0;
            }

    load_chunk(0, 0);
    load_chunk(1, 1);

    const int arow  = lane & 15;
    const int akoff = (lane >> 4) * 16;

    int stage = 0;
    for (int c = 0; c < 6; ++c) {
        if (c < 5) CP_WAIT1(); else CP_WAIT0();
        __syncthreads();
        if (c + 2 < 6) {
            int s2 = stage + 2; if (s2 >= 3) s2 -= 3;
            load_chunk(c + 2, s2);
        }

        const uint32_t sA = sbase + (uint32_t)stage * 49152u;
        #pragma unroll
        for (int ks = 0; ks < 4; ++ks) {
            const int kbyte = ks*32;
            uint32_t a1f[2][4], a2f[2][4], bf[4];
            uint32_t adA[2], bdA;
            #pragma unroll
            for (int mi = 0; mi < 2; ++mi) {
                uint32_t off = (uint32_t)((wm + mi*16 + arow)*128 + kbyte + akoff);
                adA[mi] = sA + SMEM_SWZ(off);
                LDSM4(a1f[mi], adA[mi]);
            }
            {
                uint32_t off = (uint32_t)((wn + arow)*128 + kbyte + akoff);
                bdA = sA + 32768u + SMEM_SWZ(off);
                LDSM4(bf, bdA);
            }
            // P11
            #pragma unroll
            for (int mi = 0; mi < 2; ++mi)
                #pragma unroll
                for (int ni = 0; ni < 2; ++ni)
                    MMAI(accA[mi][ni], a1f[mi], bf[ni], bf[ni + 2]);
            // P21 (x2 * w1)
            #pragma unroll
            for (int mi = 0; mi < 2; ++mi) LDSM4(a2f[mi], adA[mi] + 16384u);
            #pragma unroll
            for (int mi = 0; mi < 2; ++mi)
                #pragma unroll
                for (int ni = 0; ni < 2; ++ni)
                    MMAI(accB[mi][ni], a2f[mi], bf[ni], bf[ni + 2]);
            // P12 (x1 * w2) and P22 (x2 * w2)
            LDSM4(bf, bdA + 8192u);
            #pragma unroll
            for (int mi = 0; mi < 2; ++mi)
                #pragma unroll
                for (int ni = 0; ni < 2; ++ni)
                    MMAI(accB[mi][ni], a1f[mi], bf[ni], bf[ni + 2]);
            #pragma unroll
            for (int mi = 0; mi < 2; ++mi)
                #pragma unroll
                for (int ni = 0; ni < 2; ++ni)
                    MMAI(accC[mi][ni], a2f[mi], bf[ni], bf[ni + 2]);
        }
        if (++stage >= 3) stage = 0;
    }

    // epilogue: combine scales, relu(+b1)*w2, reduce over e
    const float C1 = SX*SW;
    const float C2 = C1 * (1.0f/254.0f);
    const float C3 = C1 * (1.0f/64516.0f);
    #pragma unroll
    for (int mi = 0; mi < 2; ++mi) {
        float s0 = 0.f, s1 = 0.f;
        #pragma unroll
        for (int ni = 0; ni < 2; ++ni) {
            int e  = wn + ni*8 + (lane & 3)*2;
            float b0 = sb1[e], b1v = sb1[e+1];
            float w0 = sw2[e], w1v = sw2[e+1];
            #pragma unroll
            for (int q = 0; q < 4; ++q) {
                float h = fmaf((float)accA[mi][ni][q], C1,
                          fmaf((float)accB[mi][ni][q], C2,
                               (float)accC[mi][ni][q] * C3));
                float bb = (q & 1) ? b1v : b0;
                float ww = (q & 1) ? w1v : w0;
                float r  = fmaxf(h + bb, 0.f) * ww;
                if (q < 2) s0 += r; else s1 += r;
            }
        }
        s0 += __shfl_xor_sync(0xffffffffu, s0, 1);
        s0 += __shfl_xor_sync(0xffffffffu, s0, 2);
        s1 += __shfl_xor_sync(0xffffffffu, s1, 1);
        s1 += __shfl_xor_sync(0xffffffffu, s1, 2);
        if ((lane & 3) == 0) {
            int r = wm + mi*16 + (lane >> 2);
            atomicAdd(&spart[r], s0);
            atomicAdd(&spart[r + 8], s1);
        }
    }
    __syncthreads();
    if (tid < 128) g_partial[nt*16384 + m0 + tid] = spart[tid];
}

// =================================================================
// K2: sum partials -> sigmoid -> score; per-batch top-512 bitonic.
// =================================================================
__global__ void k2_topk(const float* __restrict__ b2, int b_base)
{
    __shared__ unsigned long long keys[1024];
    __shared__ int msk[1024];
    __shared__ int pA[1024];
    __shared__ int pB[1024];
    const int b = b_base + blockIdx.x, tid = threadIdx.x;
    const float b2v = b2[0];

    for (int i = tid; i < 1024; i += 512) {
        int gt = b*NN + i;
        float pre = b2v;
        #pragma unroll
        for (int q = 0; q < 12; ++q) pre += g_partial[q*16384 + gt];
        float sc = 1.0f / (1.0f + expf(-pre));
        g_score[gt] = sc;
        unsigned u = __float_as_uint(sc);
        u = (u & 0x80000000u) ? ~u : (u | 0x80000000u);
        keys[i] = ((unsigned long long)u << 32) | (unsigned)(1023 - i);
    }
    __syncthreads();

    for (int k = 2; k <= 1024; k <<= 1)
        for (int j = k >> 1; j > 0; j >>= 1) {
            for (int i = tid; i < 1024; i += 512) {
                int ixj = i ^ j;
                if (ixj > i) {
                    bool up = ((i & k) == 0);
                    unsigned long long a = keys[i], c = keys[ixj];
                    if ((a > c) == up) { keys[i] = c; keys[ixj] = a; }
                }
            }
            __syncthreads();
        }

    for (int i = tid; i < 1024; i += 512) {
        int n = 1023 - (int)(unsigned)(keys[i] & 0xffffffffull);
        msk[n] = (i >= 512) ? 1 : 0;
    }
    __syncthreads();
    for (int i = tid; i < 1024; i += 512) { g_mask[b*NN + i] = msk[i]; pA[i] = msk[i]; }
    __syncthreads();

    int* src = pA; int* dst = pB;
    for (int off = 1; off < 1024; off <<= 1) {
        for (int i = tid; i < 1024; i += 512)
            dst[i] = src[i] + ((i >= off) ? src[i - off] : 0);
        __syncthreads();
        int* t = src; src = dst; dst = t;
    }
    for (int i = tid; i < 1024; i += 512)
        if (msk[i]) g_topidx[b*TK + src[i] - 1] = i;

    if (tid == 0) {
        unsigned umax = (unsigned)(keys[1023] >> 32);
        unsigned umin = (unsigned)(keys[0]    >> 32);
        g_bmax[b] = (umax & 0x80000000u) ? __uint_as_float(umax ^ 0x80000000u)
                                         : __uint_as_float(~umax);
        g_bmin[b] = (umin & 0x80000000u) ? __uint_as_float(umin ^ 0x80000000u)
                                         : __uint_as_float(~umin);
    }
}

// =================================================================
// K3: W = wp @ conv_w^T  (768x256 · 256x256), tiled 64x64.
// =================================================================
__global__ void k3_W(const float* __restrict__ wp, const float* __restrict__ conv_w)
{
    __shared__ float As[32*68];
    __shared__ float Bs[32*68];
    const int tid = threadIdx.x;
    const int tx  = tid & 15, ty = tid >> 4;
    const int o0  = blockIdx.x * 64;
    const int d0  = blockIdx.y * 64;

    float acc[4][4];
    #pragma unroll
    for (int i = 0; i < 4; ++i)
        #pragma unroll
        for (int j = 0; j < 4; ++j) acc[i][j] = 0.f;

    for (int k0 = 0; k0 < 256; k0 += 32) {
        #pragma unroll
        for (int q = 0; q < 8; ++q) {
            int v = tid + q*256;
            int r = v >> 5, kk = v & 31;
            As[kk*68 + r] = wp    [(size_t)(d0 + r)*256 + k0 + kk];
            Bs[kk*68 + r] = conv_w[(size_t)(o0 + r)*256 + k0 + kk];
        }
        __syncthreads();
        #pragma unroll
        for (int kk = 0; kk < 32; ++kk) {
            float a[4], bb[4];
            #pragma unroll
            for (int i = 0; i < 4; ++i) a[i]  = As[kk*68 + ty*4 + i];
            #pragma unroll
            for (int j = 0; j < 4; ++j) bb[j] = Bs[kk*68 + tx*4 + j];
            #pragma unroll
            for (int i = 0; i < 4; ++i)
                #pragma unroll
                for (int j = 0; j < 4; ++j)
                    acc[i][j] = fmaf(a[i], bb[j], acc[i][j]);
        }
        __syncthreads();
    }
    #pragma unroll
    for (int i = 0; i < 4; ++i)
        #pragma unroll
        for (int j = 0; j < 4; ++j)
            g_W[(size_t)(d0 + ty*4 + i)*256 + o0 + tx*4 + j] = acc[i][j];
}

// =================================================================
// K4: c0/c1 bias vectors (one warp per output o)
// =================================================================
__global__ void k4_c(const float* __restrict__ conv_w, const float* __restrict__ bp,
                     const float* __restrict__ mt, const float* __restrict__ conv_b)
{
    const int o    = blockIdx.x * 8 + (threadIdx.x >> 5);
    const int lane = threadIdx.x & 31;
    float s0 = 0.f, s1 = 0.f;
    #pragma unroll
    for (int z = lane; z < 256; z += 32) {
        float cw = conv_w[o*256 + z];
        s0 = fmaf(cw, bp[z], s0);
        s1 = fmaf(cw, mt[z], s1);
    }
    for (int off = 16; off; off >>= 1) {
        s0 += __shfl_xor_sync(0xffffffffu, s0, off);
        s1 += __shfl_xor_sync(0xffffffffu, s1, off);
    }
    if (lane == 0) {
        g_c0[o] = s0 + conv_b[o];
        g_c1[o] = s1 + conv_b[o];
    }
}

// =================================================================
// K5: fill dec with constant non-top column c1
// =================================================================
__global__ void k5_fill(float* __restrict__ dec)
{
    int b = blockIdx.x >> 8, o = blockIdx.x & 255;
    float c = g_c1[o];
    float4 f = make_float4(c, c, c, c);
    float4* row = (float4*)(dec + ((size_t)b*256 + o)*1024);
    row[threadIdx.x] = f;
}

// =================================================================
// K6: binary_map + score_map
// =================================================================
__global__ void k6_maps(float* __restrict__ bin, float* __restrict__ scm)
{
    const int b = blockIdx.x >> 9;
    const int y = blockIdx.x & 511;
    float mn = g_bmin[0], mx = g_bmax[0];
    #pragma unroll
    for (int k = 1; k < 16; ++k) { mn = fminf(mn, g_bmin[k]); mx = fmaxf(mx, g_bmax[k]); }
    float inv = 1.0f / fmaxf(mx - mn, 1e-5f);

    const int x = threadIdx.x;
    const int n = (y >> 4)*32 + (x >> 4);
    size_t o = (size_t)b*262144 + (size_t)y*512 + x;
    bin[o] = g_mask[b*NN + n] ? 1.0f : 0.0f;
    scm[o] = (g_score[b*NN + n] - mn) * inv;
}

// =================================================================
// K7G: dec top columns via bf16 HMMA (R11 shape, unchanged).
// =================================================================
__global__ void __launch_bounds__(512, 1)
k7g_dec(float* __restrict__ dec, int blk_base)
{
    extern __shared__ char dsm[];
    __shared__ int   tok[128];
    __shared__ float scl[128];
    __shared__ float muv[128];
    __shared__ float swc[128];
    __shared__ float sc0[128];

    const int tid  = threadIdx.x;
    const int wid  = tid >> 5, lane = tid & 31;
    const int blk  = blk_base + blockIdx.x;
    const int mtile = blk >> 1;
    const int ntile = blk & 1;
    const int b    = mtile >> 2;
    const int s0   = (mtile & 3) * 128;
    const int o0   = ntile * 128;
    const int wm   = (wid & 3) * 32;
    const int wn   = (wid >> 2) * 32;

    const uint32_t sbase = (smem_u32(dsm) + 1023u) & ~1023u;

    if (tid < 128) {
        int t = g_topidx[b*TK + s0 + tid];
        tok[tid] = t;
        muv[tid] = g_mu[b*NN + t];
        scl[tid] = g_rstd[b*NN + t] * g_score[b*NN + t];
        swc[tid] = g_wcol[o0 + tid];
        sc0[tid] = g_c0[o0 + tid];
    }
    __syncthreads();

    const char* xh = (const char*)g_xh;
    const char* xl = (const char*)g_xl;
    const char* wh = (const char*)g_w2h;
    const char* wl = (const char*)g_w2l;

    auto load_chunk = [&](int c, int st) {
        const uint32_t sA = sbase + (uint32_t)st * 65536u;
        const int kb = c * 128;
        #pragma unroll
        for (int q = 0; q < 4; ++q) {
            int idx  = tid + q*512;
            int half = idx >> 10, rem = idx & 1023;
            int r = rem >> 3, ci = rem & 7;
            uint32_t off = (uint32_t)(r*128 + ci*16);
            uint32_t dst = sA + (uint32_t)half*16384u + SMEM_SWZ(off);
            size_t grow = (size_t)(b*1024 + tok[r]);
            const char* src = (half ? xl : xh) + grow*1536 + kb + ci*16;
            CP16(dst, src);
        }
        #pragma unroll
        for (int q = 0; q < 4; ++q) {
            int idx  = tid + q*512;
            int half = idx >> 10, rem = idx & 1023;
            int r = rem >> 3, ci = rem & 7;
            uint32_t off = (uint32_t)(r*128 + ci*16);
            uint32_t dst = sA + 32768u + (uint32_t)half*16384u + SMEM_SWZ(off);
            const char* src = (half ? wl : wh) + (size_t)(o0 + r)*1536 + kb + ci*16;
            CP16(dst, src);
        }
        CP_COMMIT();
    };

    float acc[2][4][4];
    #pragma unroll
    for (int i = 0; i < 2; ++i)
        #pragma unroll
        for (int j = 0; j < 4; ++j)
            #pragma unroll
            for (int q = 0; q < 4; ++q) acc[i][j][q] = 0.f;

    load_chunk(0, 0);

    const int arow  = lane & 15;
    const int akoff = (lane >> 4) * 16;

    for (int c = 0; c < 12; ++c) {
        if (c + 1 < 12) { load_chunk(c + 1, (c + 1) & 1); CP_WAIT1(); }
        else            { CP_WAIT0(); }
        __syncthreads();

        const uint32_t sA = sbase + (uint32_t)(c & 1) * 65536u;
        #pragma unroll
        for (int ks = 0; ks < 4; ++ks) {
            const int kbyte = ks*32;
            uint32_t ah[2][4], al[2][4], bh[2][4], bl[2][4];
            #pragma unroll
            for (int mi = 0; mi < 2; ++mi) {
                uint32_t off = (uint32_t)((wm + mi*16 + arow)*128 + kbyte + akoff);
                uint32_t ad  = sA + SMEM_SWZ(off);
                LDSM4(ah[mi], ad);
                LDSM4(al[mi], ad + 16384u);
            }
            #pragma unroll
            for (int bi = 0; bi < 2; ++bi) {
                uint32_t off = (uint32_t)((wn + bi*16 + arow)*128 + kbyte + akoff);
                uint32_t bd  = sA + 32768u + SMEM_SWZ(off);
                LDSM4(bh[bi], bd);
                LDSM4(bl[bi], bd + 16384u);
            }
            #pragma unroll
            for (int mi = 0; mi < 2; ++mi)
                #pragma unroll
                for (int ni = 0; ni < 4; ++ni) {
                    const int bi = ni >> 1, s = ni & 1;
                    MMA16816(acc[mi][ni], ah[mi], bh[bi][s], bh[bi][s + 2]);
                }
            #pragma unroll
            for (int mi = 0; mi < 2; ++mi)
                #pragma unroll
                for (int ni = 0; ni < 4; ++ni) {
                    const int bi = ni >> 1, s = ni & 1;
                    MMA16816(acc[mi][ni], al[mi], bh[bi][s], bh[bi][s + 2]);
                }
            #pragma unroll
            for (int mi = 0; mi < 2; ++mi)
                #pragma unroll
                for (int ni = 0; ni < 4; ++ni) {
                    const int bi = ni >> 1, s = ni & 1;
                    MMA16816(acc[mi][ni], ah[mi], bl[bi][s], bl[bi][s + 2]);
                }
        }
        __syncthreads();
    }

    float* decb = dec + (size_t)(b*256 + o0)*1024;
    #pragma unroll
    for (int mi = 0; mi < 2; ++mi) {
        int r0 = wm + mi*16 + (lane >> 2);
        int r1 = r0 + 8;
        float sc_0 = scl[r0], mu_0 = muv[r0]; int t0 = tok[r0];
        float sc_1 = scl[r1], mu_1 = muv[r1]; int t1 = tok[r1];
        #pragma unroll
        for (int ni = 0; ni < 4; ++ni) {
            int o = wn + ni*8 + (lane & 3)*2;
            float wc0 = swc[o], wc1 = swc[o+1];
            float c00 = sc0[o], c01 = sc0[o+1];
            float* cc = acc[mi][ni];
            decb[(size_t)o*1024 + t0]     = fmaf(sc_0, cc[0] - mu_0*wc0, c00);
            decb[(size_t)(o+1)*1024 + t0] = fmaf(sc_0, cc[1] - mu_0*wc1, c01);
            decb[(size_t)o*1024 + t1]     = fmaf(sc_1, cc[2] - mu_1*wc0, c00);
            decb[(size_t)(o+1)*1024 + t1] = fmaf(sc_1, cc[3] - mu_1*wc1, c01);
        }
    }
}

// =================================================================
extern "C" void kernel_launch(void* const* d_in, const int* in_sizes, int n_in,
                              void* d_out, int out_size)
{
    const float* IF     = (const float*)d_in[0];
    const float* w1     = (const float*)d_in[1];
    const float* b1     = (const float*)d_in[2];
    const float* w2     = (const float*)d_in[3];
    const float* b2     = (const float*)d_in[4];
    const float* wp     = (const float*)d_in[5];
    const float* bp     = (const float*)d_in[6];
    const float* mt     = (const float*)d_in[7];
    const float* conv_w = (const float*)d_in[8];
    const float* conv_b = (const float*)d_in[9];

    float* out = (float*)d_out;
    float* dec = out;                 // 16*256*1024
    float* bin = out + 4194304;       // 16*1*512*512
    float* scm = out + 8388608;       // 16*1*512*512

    const size_t smemX  = (size_t)768*64*sizeof(float);   // 196608
    const size_t smemG1 = 3*49152 + 1024;                 // 148480
    const size_t smemG7 = 2*65536 + 1024;                 // 132096
    cudaFuncSetAttribute(kc_convx, cudaFuncAttributeMaxDynamicSharedMemorySize, (int)smemX);
    cudaFuncSetAttribute(k1g_gemm, cudaFuncAttributeMaxDynamicSharedMemorySize, (int)smemG1);
    cudaFuncSetAttribute(k7g_dec,  cudaFuncAttributeMaxDynamicSharedMemorySize, (int)smemG7);

    // one-time host resources (streams/events, not device memory)
    static cudaStream_t s1 = nullptr, s2 = nullptr, s3 = nullptr;
    static cudaEvent_t  eF = nullptr, eW = nullptr, eS2 = nullptr,
                        eX0 = nullptr, eG0 = nullptr, eK2a = nullptr,
                        eD0 = nullptr, eK2b = nullptr, eK6 = nullptr;
    if (s1 == nullptr) {
        cudaStreamCreateWithFlags(&s1, cudaStreamNonBlocking);
        cudaStreamCreateWithFlags(&s2, cudaStreamNonBlocking);
        cudaStreamCreateWithFlags(&s3, cudaStreamNonBlocking);
        cudaEventCreateWithFlags(&eF,   cudaEventDisableTiming);
        cudaEventCreateWithFlags(&eW,   cudaEventDisableTiming);
        cudaEventCreateWithFlags(&eS2,  cudaEventDisableTiming);
        cudaEventCreateWithFlags(&eX0,  cudaEventDisableTiming);
        cudaEventCreateWithFlags(&eG0,  cudaEventDisableTiming);
        cudaEventCreateWithFlags(&eK2a, cudaEventDisableTiming);
        cudaEventCreateWithFlags(&eD0,  cudaEventDisableTiming);
        cudaEventCreateWithFlags(&eK2b, cudaEventDisableTiming);
        cudaEventCreateWithFlags(&eK6,  cudaEventDisableTiming);
    }

    // fork side streams off the origin (capture) stream
    cudaEventRecord(eF, 0);
    cudaStreamWaitEvent(s1, eF, 0);
    cudaStreamWaitEvent(s2, eF, 0);
    cudaStreamWaitEvent(s3, eF, 0);

    // s1: w1 int8 convert (needed by k1g)
    kc_convw<<<dim3(24, 24), dim3(32, 8), 0, s1>>>(w1);
    cudaEventRecord(eW, s1);

    // s2: side chain for k7g (independent of k1g)
    k3_W<<<dim3(4, 12), 256, 0, s2>>>(wp, conv_w);
    kc_convw2<<<dim3(24, 8), dim3(32, 8), 0, s2>>>();
    kwcol<<<1, 1024, 0, s2>>>();
    k4_c<<<32, 256, 0, s2>>>(conv_w, bp, mt, conv_b);
    k5_fill<<<4096, 256, 0, s2>>>(dec);
    cudaEventRecord(eS2, s2);

    // origin: convert x, half by half
    kc_convx<<<128, 512, smemX, 0>>>(IF, 0);
    cudaEventRecord(eX0, 0);
    kc_convx<<<128, 512, smemX, 0>>>(IF, 128);

    // s1: GEMM half 0 (m-tiles 0..63) once convx half 0 done (convw program-ordered on s1)
    cudaStreamWaitEvent(s1, eX0, 0);
    k1g_gemm<<<768, 512, smemG1, s1>>>(b1, w2, 0);
    cudaEventRecord(eG0, s1);

    // origin: GEMM half 1
    cudaStreamWaitEvent(0, eW, 0);
    k1g_gemm<<<768, 512, smemG1, 0>>>(b1, w2, 64);

    // s3: batches 0-7 tail
    cudaStreamWaitEvent(s3, eG0, 0);
    k2_topk<<<8, 512, 0, s3>>>(b2, 0);
    cudaEventRecord(eK2a, s3);
    cudaStreamWaitEvent(s3, eS2, 0);
    k7g_dec<<<64, 512, smemG7, s3>>>(dec, 0);
    cudaEventRecord(eD0, s3);

    // origin: batches 8-15 tail
    k2_topk<<<8, 512, 0, 0>>>(b2, 8);
    cudaEventRecord(eK2b, 0);

    // s1: maps need min/max over ALL batches
    cudaStreamWaitEvent(s1, eK2a, 0);
    cudaStreamWaitEvent(s1, eK2b, 0);
    k6_maps<<<8192, 512, 0, s1>>>(bin, scm);
    cudaEventRecord(eK6, s1);

    // origin: dec top columns for batches 8-15
    cudaStreamWaitEvent(0, eS2, 0);
    k7g_dec<<<64, 512, smemG7, 0>>>(dec, 64);

    // join all side work back into origin
    cudaStreamWaitEvent(0, eD0, 0);
    cudaStreamWaitEvent(0, eK6, 0);
}

// round 14
// speedup vs baseline: 2.2764x; 2.2764x over previous
#include <cuda_runtime.h>
#include <cuda_bf16.h>
#include <stdint.h>
#include <math.h>

#define BN   16
#define DD   768
#define NN   1024
#define ZZ   256
#define TK   512

// -------- scratch (device globals; no allocation allowed) --------
__device__ float g_score[BN*NN];
__device__ float g_mu[BN*NN];
__device__ float g_rstd[BN*NN];
__device__ int   g_topidx[BN*TK];
__device__ int   g_mask[BN*NN];
__device__ float g_bmin[BN];
__device__ float g_bmax[BN];
__device__ float g_W[DD*ZZ];
__device__ float g_c0[ZZ];
__device__ float g_c1[ZZ];
__device__ float g_wcol[ZZ];
// bf16 split operands + GEMM partials
__device__ __align__(16) __nv_bfloat16 g_xh[16384*768];   // x hi  [token][d]
__device__ __align__(16) __nv_bfloat16 g_xl[16384*768];   // x lo
__device__ __align__(16) __nv_bfloat16 g_wth[768*768];    // w1^T hi [e][k]
__device__ __align__(16) __nv_bfloat16 g_wtl[768*768];    // w1^T lo
__device__ __align__(16) __nv_bfloat16 g_w2h[256*768];    // W^T hi [o][d]
__device__ __align__(16) __nv_bfloat16 g_w2l[256*768];    // W^T lo
__device__ float g_partial[6*16384];                      // per n-tile token partials

// ---------------- smem / async helpers ----------------
__device__ __forceinline__ uint32_t smem_u32(const void* p) {
    uint32_t a;
    asm("{ .reg .u64 t; cvta.to.shared.u64 t, %1; cvt.u32.u64 %0, t; }" : "=r"(a) : "l"(p));
    return a;
}
#define SMEM_SWZ(off) ((off) ^ (((off) >> 3) & 0x70))
#define CP16(dst, src)   asm volatile("cp.async.cg.shared.global [%0], [%1], 16;" :: "r"(dst), "l"(src))
#define CP_COMMIT()      asm volatile("cp.async.commit_group;" ::: "memory")
#define CP_WAIT0()       asm volatile("cp.async.wait_group 0;" ::: "memory")
#define CP_WAIT1()       asm volatile("cp.async.wait_group 1;" ::: "memory")

#define LDSM4(r, a) \
    asm volatile("ldmatrix.sync.aligned.m8n8.x4.shared.b16 {%0,%1,%2,%3}, [%4];" \
        : "=r"((r)[0]), "=r"((r)[1]), "=r"((r)[2]), "=r"((r)[3]) : "r"(a))

#define MMA16816(d, a, b0, b1) \
    asm volatile("mma.sync.aligned.m16n8k16.row.col.f32.bf16.bf16.f32 " \
        "{%0,%1,%2,%3},{%4,%5,%6,%7},{%8,%9},{%0,%1,%2,%3};" \
        : "+f"((d)[0]), "+f"((d)[1]), "+f"((d)[2]), "+f"((d)[3]) \
        : "r"((a)[0]), "r"((a)[1]), "r"((a)[2]), "r"((a)[3]), "r"(b0), "r"(b1))

// =================================================================
// KCW: transpose + split w1 -> g_wth/g_wtl [e][k]
// =================================================================
__global__ void kc_convw(const float* __restrict__ w1)
{
    __shared__ float ts[32][33];
    const int tx = threadIdx.x, ty = threadIdx.y;
    const int k0 = blockIdx.x * 32, e0 = blockIdx.y * 32;
    #pragma unroll
    for (int j = 0; j < 32; j += 8)
        ts[ty + j][tx] = w1[(size_t)(k0 + ty + j)*768 + e0 + tx];
    __syncthreads();
    #pragma unroll
    for (int j = 0; j < 32; j += 8) {
        float v = ts[tx][ty + j];
        size_t o = (size_t)(e0 + ty + j)*768 + k0 + tx;
        __nv_bfloat16 h = __float2bfloat16(v);
        g_wth[o] = h;
        g_wtl[o] = __float2bfloat16(v - __bfloat162float(h));
    }
}

// =================================================================
// KCW2: transpose + split g_W[d][o] -> g_w2h/g_w2l [o][d]
// =================================================================
__global__ void kc_convw2()
{
    __shared__ float ts[32][33];
    const int tx = threadIdx.x, ty = threadIdx.y;
    const int d0 = blockIdx.x * 32, o0 = blockIdx.y * 32;
    #pragma unroll
    for (int j = 0; j < 32; j += 8)
        ts[ty + j][tx] = g_W[(size_t)(d0 + ty + j)*256 + o0 + tx];
    __syncthreads();
    #pragma unroll
    for (int j = 0; j < 32; j += 8) {
        float v = ts[tx][ty + j];
        size_t o = (size_t)(o0 + ty + j)*768 + d0 + tx;
        __nv_bfloat16 h = __float2bfloat16(v);
        g_w2h[o] = h;
        g_w2l[o] = __float2bfloat16(v - __bfloat162float(h));
    }
}

// =================================================================
// KWCOL: g_wcol[o] = sum_d W[d][o]  (1024 threads, 4 row-chunks)
// =================================================================
__global__ void kwcol()
{
    __shared__ float red[4][256];
    const int o = threadIdx.x & 255, ch = threadIdx.x >> 8;
    float s = 0.f;
    #pragma unroll 8
    for (int d = ch*192; d < (ch+1)*192; ++d) s += g_W[d*256 + o];
    red[ch][o] = s;
    __syncthreads();
    if (ch == 0) g_wcol[o] = red[0][o] + red[1][o] + red[2][o] + red[3][o];
}

// =================================================================
// KCX: transpose x, compute mu/rstd, split to bf16 hi/lo [token][d]
// =================================================================
__global__ void __launch_bounds__(512, 1)
kc_convx(const float* __restrict__ IF, int blk_base)
{
    extern __shared__ float xs[];          // [d][t] : 768 x 64
    const int tid = threadIdx.x;
    const int ty  = tid >> 5, tx = tid & 31;
    const int blk = blk_base + blockIdx.x;
    const int b   = blk >> 4;
    const int n0  = (blk & 15) << 6;

    const float4* base4 = (const float4*)(IF + (size_t)b * DD * NN);
    const int n04 = n0 >> 2;
    for (int v = tid; v < 64*768/4; v += 512) {
        int d  = v >> 4;
        int t4 = v & 15;
        float4 f = base4[(size_t)d*256 + n04 + t4];
        float2* row = (float2*)(xs + d*64);
        row[t4*2 + 0] = make_float2(f.x, f.y);
        row[t4*2 + 1] = make_float2(f.z, f.w);
    }
    __syncthreads();

    const float2* xs2 = (const float2*)xs;
    for (int i = 0; i < 2; ++i) {
        int tp = ty*2 + i;
        float sx = 0.f, sy = 0.f, ssx = 0.f, ssy = 0.f;
        for (int d = tx; d < 768; d += 32) {
            float2 v = xs2[d*32 + tp];
            sx += v.x; ssx = fmaf(v.x, v.x, ssx);
            sy += v.y; ssy = fmaf(v.y, v.y, ssy);
        }
        for (int off = 16; off; off >>= 1) {
            sx  += __shfl_xor_sync(0xffffffffu, sx,  off);
            sy  += __shfl_xor_sync(0xffffffffu, sy,  off);
            ssx += __shfl_xor_sync(0xffffffffu, ssx, off);
            ssy += __shfl_xor_sync(0xffffffffu, ssy, off);
        }
        if (tx == 0) {
            float mux = sx * (1.0f/768.0f);
            float muy = sy * (1.0f/768.0f);
            g_mu  [b*NN + n0 + 2*tp + 0] = mux;
            g_mu  [b*NN + n0 + 2*tp + 1] = muy;
            g_rstd[b*NN + n0 + 2*tp + 0] = rsqrtf(ssx*(1.0f/768.0f) - mux*mux + 1e-5f);
            g_rstd[b*NN + n0 + 2*tp + 1] = rsqrtf(ssy*(1.0f/768.0f) - muy*muy + 1e-5f);
        }
    }

    const int t  = tid & 63, dq = tid >> 6;
    const int gtok = b*1024 + n0 + t;
    uint4* oh = (uint4*)(g_xh + (size_t)gtok*768);
    uint4* ol = (uint4*)(g_xl + (size_t)gtok*768);
    for (int d8 = dq; d8 < 96; d8 += 8) {
        union { __nv_bfloat16 h[8]; uint4 u; } Uh, Ul;
        #pragma unroll
        for (int i = 0; i < 8; ++i) {
            float v = xs[(d8*8 + i)*64 + t];
            __nv_bfloat16 h = __float2bfloat16(v);
            Uh.h[i] = h;
            Ul.h[i] = __float2bfloat16(v - __bfloat162float(h));
        }
        oh[d8] = Uh.u;
        ol[d8] = Ul.u;
    }
}

// =================================================================
// K1G: HMMA split GEMM (R9/R11 shape): 512 threads, 16 warps
// (4m x 4n), warp 32x32, BK=64, 3-stage / 1 barrier per chunk.
// =================================================================
__global__ void __launch_bounds__(512, 1)
k1g_gemm(const float* __restrict__ b1, const float* __restrict__ w2, int m_base)
{
    extern __shared__ char dsm[];
    __shared__ float sb1[128];
    __shared__ float sw2[128];
    __shared__ float spart[128];

    const int tid  = threadIdx.x;
    const int wid  = tid >> 5, lane = tid & 31;
    const int mt   = m_base + blockIdx.x / 6;
    const int nt   = blockIdx.x % 6;
    const int m0   = mt * 128;
    const int e0   = nt * 128;
    const int wm   = (wid & 3) * 32;
    const int wn   = (wid >> 2) * 32;

    const uint32_t sbase = (smem_u32(dsm) + 1023u) & ~1023u;

    if (tid < 128) {
        sb1[tid]   = b1[e0 + tid];
        sw2[tid]   = w2[e0 + tid];
        spart[tid] = 0.f;
    }

    const char* xh = (const char*)g_xh;
    const char* xl = (const char*)g_xl;
    const char* wh = (const char*)g_wth;
    const char* wl = (const char*)g_wtl;

    auto load_chunk = [&](int c, int st) {
        const uint32_t sA = sbase + (uint32_t)st * 65536u;
        const int kb = c * 128;
        #pragma unroll
        for (int q = 0; q < 4; ++q) {
            int idx  = tid + q*512;
            int half = idx >> 10, rem = idx & 1023;
            int r = rem >> 3, ci = rem & 7;
            uint32_t off = (uint32_t)(r*128 + ci*16);
            uint32_t dst = sA + (uint32_t)half*16384u + SMEM_SWZ(off);
            const char* src = (half ? xl : xh) + (size_t)(m0 + r)*1536 + kb + ci*16;
            CP16(dst, src);
        }
        #pragma unroll
        for (int q = 0; q < 4; ++q) {
            int idx  = tid + q*512;
            int half = idx >> 10, rem = idx & 1023;
            int r = rem >> 3, ci = rem & 7;
            uint32_t off = (uint32_t)(r*128 + ci*16);
            uint32_t dst = sA + 32768u + (uint32_t)half*16384u + SMEM_SWZ(off);
            const char* src = (half ? wl : wh) + (size_t)(e0 + r)*1536 + kb + ci*16;
            CP16(dst, src);
        }
        CP_COMMIT();
    };

    float acc[2][4][4];
    #pragma unroll
    for (int i = 0; i < 2; ++i)
        #pragma unroll
        for (int j = 0; j < 4; ++j)
            #pragma unroll
            for (int q = 0; q < 4; ++q) acc[i][j][q] = 0.f;

    load_chunk(0, 0);
    load_chunk(1, 1);

    const int arow  = lane & 15;
    const int akoff = (lane >> 4) * 16;

    int stage = 0;
    for (int c = 0; c < 12; ++c) {
        if (c < 11) CP_WAIT1(); else CP_WAIT0();
        __syncthreads();
        if (c + 2 < 12) {
            int s2 = stage + 2; if (s2 >= 3) s2 -= 3;
            load_chunk(c + 2, s2);
        }

        const uint32_t sA = sbase + (uint32_t)stage * 65536u;
        #pragma unroll
        for (int ks = 0; ks < 4; ++ks) {
            const int kbyte = ks*32;
            uint32_t ah[2][4], al[2][4], bh[2][4], bl[2][4];
            #pragma unroll
            for (int mi = 0; mi < 2; ++mi) {
                uint32_t off = (uint32_t)((wm + mi*16 + arow)*128 + kbyte + akoff);
                uint32_t ad  = sA + SMEM_SWZ(off);
                LDSM4(ah[mi], ad);
                LDSM4(al[mi], ad + 16384u);
            }
            #pragma unroll
            for (int bi = 0; bi < 2; ++bi) {
                uint32_t off = (uint32_t)((wn + bi*16 + arow)*128 + kbyte + akoff);
                uint32_t bd  = sA + 32768u + SMEM_SWZ(off);
                LDSM4(bh[bi], bd);
                LDSM4(bl[bi], bd + 16384u);
            }
            #pragma unroll
            for (int mi = 0; mi < 2; ++mi)
                #pragma unroll
                for (int ni = 0; ni < 4; ++ni) {
                    const int bi = ni >> 1, s = ni & 1;
                    MMA16816(acc[mi][ni], ah[mi], bh[bi][s], bh[bi][s + 2]);
                }
            #pragma unroll
            for (int mi = 0; mi < 2; ++mi)
                #pragma unroll
                for (int ni = 0; ni < 4; ++ni) {
                    const int bi = ni >> 1, s = ni & 1;
                    MMA16816(acc[mi][ni], al[mi], bh[bi][s], bh[bi][s + 2]);
                }
            #pragma unroll
            for (int mi = 0; mi < 2; ++mi)
                #pragma unroll
                for (int ni = 0; ni < 4; ++ni) {
                    const int bi = ni >> 1, s = ni & 1;
                    MMA16816(acc[mi][ni], ah[mi], bl[bi][s], bl[bi][s + 2]);
                }
        }
        if (++stage >= 3) stage = 0;
    }

    #pragma unroll
    for (int mi = 0; mi < 2; ++mi) {
        float s0 = 0.f, s1 = 0.f;
        #pragma unroll
        for (int ni = 0; ni < 4; ++ni) {
            int e  = wn + ni*8 + (lane & 3)*2;
            float b0 = sb1[e], b1v = sb1[e+1];
            float w0 = sw2[e], w1v = sw2[e+1];
            float* cc = acc[mi][ni];
            s0 = fmaf(fmaxf(cc[0] + b0, 0.f), w0, s0);
            s0 = fmaf(fmaxf(cc[1] + b1v, 0.f), w1v, s0);
            s1 = fmaf(fmaxf(cc[2] + b0, 0.f), w0, s1);
            s1 = fmaf(fmaxf(cc[3] + b1v, 0.f), w1v, s1);
        }
        s0 += __shfl_xor_sync(0xffffffffu, s0, 1);
        s0 += __shfl_xor_sync(0xffffffffu, s0, 2);
        s1 += __shfl_xor_sync(0xffffffffu, s1, 1);
        s1 += __shfl_xor_sync(0xffffffffu, s1, 2);
        if ((lane & 3) == 0) {
            int r = wm + mi*16 + (lane >> 2);
            atomicAdd(&spart[r], s0);
            atomicAdd(&spart[r + 8], s1);
        }
    }
    __syncthreads();
    if (tid < 128) g_partial[nt*16384 + m0 + tid] = spart[tid];
}

// =================================================================
// K2: sum partials -> sigmoid -> score; per-batch top-512 bitonic.
// =================================================================
__global__ void k2_topk(const float* __restrict__ b2, int b_base)
{
    __shared__ unsigned long long keys[1024];
    __shared__ int msk[1024];
    __shared__ int pA[1024];
    __shared__ int pB[1024];
    const int b = b_base + blockIdx.x, tid = threadIdx.x;
    const float b2v = b2[0];

    for (int i = tid; i < 1024; i += 512) {
        int gt = b*NN + i;
        float pre = b2v;
        #pragma unroll
        for (int q = 0; q < 6; ++q) pre += g_partial[q*16384 + gt];
        float sc = 1.0f / (1.0f + expf(-pre));
        g_score[gt] = sc;
        unsigned u = __float_as_uint(sc);
        u = (u & 0x80000000u) ? ~u : (u | 0x80000000u);
        keys[i] = ((unsigned long long)u << 32) | (unsigned)(1023 - i);
    }
    __syncthreads();

    for (int k = 2; k <= 1024; k <<= 1)
        for (int j = k >> 1; j > 0; j >>= 1) {
            for (int i = tid; i < 1024; i += 512) {
                int ixj = i ^ j;
                if (ixj > i) {
                    bool up = ((i & k) == 0);
                    unsigned long long a = keys[i], c = keys[ixj];
                    if ((a > c) == up) { keys[i] = c; keys[ixj] = a; }
                }
            }
            __syncthreads();
        }

    for (int i = tid; i < 1024; i += 512) {
        int n = 1023 - (int)(unsigned)(keys[i] & 0xffffffffull);
        msk[n] = (i >= 512) ? 1 : 0;
    }
    __syncthreads();
    for (int i = tid; i < 1024; i += 512) { g_mask[b*NN + i] = msk[i]; pA[i] = msk[i]; }
    __syncthreads();

    int* src = pA; int* dst = pB;
    for (int off = 1; off < 1024; off <<= 1) {
        for (int i = tid; i < 1024; i += 512)
            dst[i] = src[i] + ((i >= off) ? src[i - off] : 0);
        __syncthreads();
        int* t = src; src = dst; dst = t;
    }
    for (int i = tid; i < 1024; i += 512)
        if (msk[i]) g_topidx[b*TK + src[i] - 1] = i;

    if (tid == 0) {
        unsigned umax = (unsigned)(keys[1023] >> 32);
        unsigned umin = (unsigned)(keys[0]    >> 32);
        g_bmax[b] = (umax & 0x80000000u) ? __uint_as_float(umax ^ 0x80000000u)
                                         : __uint_as_float(~umax);
        g_bmin[b] = (umin & 0x80000000u) ? __uint_as_float(umin ^ 0x80000000u)
                                         : __uint_as_float(~umin);
    }
}

// =================================================================
// K3: W = wp @ conv_w^T  (768x256 · 256x256), tiled 64x64.
// =================================================================
__global__ void k3_W(const float* __restrict__ wp, const float* __restrict__ conv_w)
{
    __shared__ float As[32*68];
    __shared__ float Bs[32*68];
    const int tid = threadIdx.x;
    const int tx  = tid & 15, ty = tid >> 4;
    const int o0  = blockIdx.x * 64;
    const int d0  = blockIdx.y * 64;

    float acc[4][4];
    #pragma unroll
    for (int i = 0; i < 4; ++i)
        #pragma unroll
        for (int j = 0; j < 4; ++j) acc[i][j] = 0.f;

    for (int k0 = 0; k0 < 256; k0 += 32) {
        #pragma unroll
        for (int q = 0; q < 8; ++q) {
            int v = tid + q*256;
            int r = v >> 5, kk = v & 31;
            As[kk*68 + r] = wp    [(size_t)(d0 + r)*256 + k0 + kk];
            Bs[kk*68 + r] = conv_w[(size_t)(o0 + r)*256 + k0 + kk];
        }
        __syncthreads();
        #pragma unroll
        for (int kk = 0; kk < 32; ++kk) {
            float a[4], bb[4];
            #pragma unroll
            for (int i = 0; i < 4; ++i) a[i]  = As[kk*68 + ty*4 + i];
            #pragma unroll
            for (int j = 0; j < 4; ++j) bb[j] = Bs[kk*68 + tx*4 + j];
            #pragma unroll
            for (int i = 0; i < 4; ++i)
                #pragma unroll
                for (int j = 0; j < 4; ++j)
                    acc[i][j] = fmaf(a[i], bb[j], acc[i][j]);
        }
        __syncthreads();
    }
    #pragma unroll
    for (int i = 0; i < 4; ++i)
        #pragma unroll
        for (int j = 0; j < 4; ++j)
            g_W[(size_t)(d0 + ty*4 + i)*256 + o0 + tx*4 + j] = acc[i][j];
}

// =================================================================
// K4: c0/c1 bias vectors (one warp per output o)
// =================================================================
__global__ void k4_c(const float* __restrict__ conv_w, const float* __restrict__ bp,
                     const float* __restrict__ mt, const float* __restrict__ conv_b)
{
    const int o    = blockIdx.x * 8 + (threadIdx.x >> 5);
    const int lane = threadIdx.x & 31;
    float s0 = 0.f, s1 = 0.f;
    #pragma unroll
    for (int z = lane; z < 256; z += 32) {
        float cw = conv_w[o*256 + z];
        s0 = fmaf(cw, bp[z], s0);
        s1 = fmaf(cw, mt[z], s1);
    }
    for (int off = 16; off; off >>= 1) {
        s0 += __shfl_xor_sync(0xffffffffu, s0, off);
        s1 += __shfl_xor_sync(0xffffffffu, s1, off);
    }
    if (lane == 0) {
        g_c0[o] = s0 + conv_b[o];
        g_c1[o] = s1 + conv_b[o];
    }
}

// =================================================================
// K5: fill dec with constant non-top column c1
// =================================================================
__global__ void k5_fill(float* __restrict__ dec)
{
    int b = blockIdx.x >> 8, o = blockIdx.x & 255;
    float c = g_c1[o];
    float4 f = make_float4(c, c, c, c);
    float4* row = (float4*)(dec + ((size_t)b*256 + o)*1024);
    row[threadIdx.x] = f;
}

// =================================================================
// K6: binary_map + score_map (needs ALL batches' min/max)
// =================================================================
__global__ void k6_maps(float* __restrict__ bin, float* __restrict__ scm)
{
    const int b = blockIdx.x >> 9;
    const int y = blockIdx.x & 511;
    float mn = g_bmin[0], mx = g_bmax[0];
    #pragma unroll
    for (int k = 1; k < 16; ++k) { mn = fminf(mn, g_bmin[k]); mx = fmaxf(mx, g_bmax[k]); }
    float inv = 1.0f / fmaxf(mx - mn, 1e-5f);

    const int x = threadIdx.x;
    const int n = (y >> 4)*32 + (x >> 4);
    size_t o = (size_t)b*262144 + (size_t)y*512 + x;
    bin[o] = g_mask[b*NN + n] ? 1.0f : 0.0f;
    scm[o] = (g_score[b*NN + n] - mn) * inv;
}

// =================================================================
// K7G: dec top columns via HMMA (R9/R11 shape).
// =================================================================
__global__ void __launch_bounds__(512, 1)
k7g_dec(float* __restrict__ dec, int blk_base)
{
    extern __shared__ char dsm[];
    __shared__ int   tok[128];
    __shared__ float scl[128];
    __shared__ float muv[128];
    __shared__ float swc[128];
    __shared__ float sc0[128];

    const int tid  = threadIdx.x;
    const int wid  = tid >> 5, lane = tid & 31;
    const int blk  = blk_base + blockIdx.x;
    const int mtile = blk >> 1;
    const int ntile = blk & 1;
    const int b    = mtile >> 2;
    const int s0   = (mtile & 3) * 128;
    const int o0   = ntile * 128;
    const int wm   = (wid & 3) * 32;
    const int wn   = (wid >> 2) * 32;

    const uint32_t sbase = (smem_u32(dsm) + 1023u) & ~1023u;

    if (tid < 128) {
        int t = g_topidx[b*TK + s0 + tid];
        tok[tid] = t;
        muv[tid] = g_mu[b*NN + t];
        scl[tid] = g_rstd[b*NN + t] * g_score[b*NN + t];
        swc[tid] = g_wcol[o0 + tid];
        sc0[tid] = g_c0[o0 + tid];
    }
    __syncthreads();

    const char* xh = (const char*)g_xh;
    const char* xl = (const char*)g_xl;
    const char* wh = (const char*)g_w2h;
    const char* wl = (const char*)g_w2l;

    auto load_chunk = [&](int c, int st) {
        const uint32_t sA = sbase + (uint32_t)st * 65536u;
        const int kb = c * 128;
        #pragma unroll
        for (int q = 0; q < 4; ++q) {
            int idx  = tid + q*512;
            int half = idx >> 10, rem = idx & 1023;
            int r = rem >> 3, ci = rem & 7;
            uint32_t off = (uint32_t)(r*128 + ci*16);
            uint32_t dst = sA + (uint32_t)half*16384u + SMEM_SWZ(off);
            size_t grow = (size_t)(b*1024 + tok[r]);
            const char* src = (half ? xl : xh) + grow*1536 + kb + ci*16;
            CP16(dst, src);
        }
        #pragma unroll
        for (int q = 0; q < 4; ++q) {
            int idx  = tid + q*512;
            int half = idx >> 10, rem = idx & 1023;
            int r = rem >> 3, ci = rem & 7;
            uint32_t off = (uint32_t)(r*128 + ci*16);
            uint32_t dst = sA + 32768u + (uint32_t)half*16384u + SMEM_SWZ(off);
            const char* src = (half ? wl : wh) + (size_t)(o0 + r)*1536 + kb + ci*16;
            CP16(dst, src);
        }
        CP_COMMIT();
    };

    float acc[2][4][4];
    #pragma unroll
    for (int i = 0; i < 2; ++i)
        #pragma unroll
        for (int j = 0; j < 4; ++j)
            #pragma unroll
            for (int q = 0; q < 4; ++q) acc[i][j][q] = 0.f;

    load_chunk(0, 0);

    const int arow  = lane & 15;
    const int akoff = (lane >> 4) * 16;

    for (int c = 0; c < 12; ++c) {
        if (c + 1 < 12) { load_chunk(c + 1, (c + 1) & 1); CP_WAIT1(); }
        else            { CP_WAIT0(); }
        __syncthreads();

        const uint32_t sA = sbase + (uint32_t)(c & 1) * 65536u;
        #pragma unroll
        for (int ks = 0; ks < 4; ++ks) {
            const int kbyte = ks*32;
            uint32_t ah[2][4], al[2][4], bh[2][4], bl[2][4];
            #pragma unroll
            for (int mi = 0; mi < 2; ++mi) {
                uint32_t off = (uint32_t)((wm + mi*16 + arow)*128 + kbyte + akoff);
                uint32_t ad  = sA + SMEM_SWZ(off);
                LDSM4(ah[mi], ad);
                LDSM4(al[mi], ad + 16384u);
            }
            #pragma unroll
            for (int bi = 0; bi < 2; ++bi) {
                uint32_t off = (uint32_t)((wn + bi*16 + arow)*128 + kbyte + akoff);
                uint32_t bd  = sA + 32768u + SMEM_SWZ(off);
                LDSM4(bh[bi], bd);
                LDSM4(bl[bi], bd + 16384u);
            }
            #pragma unroll
            for (int mi = 0; mi < 2; ++mi)
                #pragma unroll
                for (int ni = 0; ni < 4; ++ni) {
                    const int bi = ni >> 1, s = ni & 1;
                    MMA16816(acc[mi][ni], ah[mi], bh[bi][s], bh[bi][s + 2]);
                }
            #pragma unroll
            for (int mi = 0; mi < 2; ++mi)
                #pragma unroll
                for (int ni = 0; ni < 4; ++ni) {
                    const int bi = ni >> 1, s = ni & 1;
                    MMA16816(acc[mi][ni], al[mi], bh[bi][s], bh[bi][s + 2]);
                }
            #pragma unroll
            for (int mi = 0; mi < 2; ++mi)
                #pragma unroll
                for (int ni = 0; ni < 4; ++ni) {
                    const int bi = ni >> 1, s = ni & 1;
                    MMA16816(acc[mi][ni], ah[mi], bl[bi][s], bl[bi][s + 2]);
                }
        }
        __syncthreads();
    }

    float* decb = dec + (size_t)(b*256 + o0)*1024;
    #pragma unroll
    for (int mi = 0; mi < 2; ++mi) {
        int r0 = wm + mi*16 + (lane >> 2);
        int r1 = r0 + 8;
        float sc_0 = scl[r0], mu_0 = muv[r0]; int t0 = tok[r0];
        float sc_1 = scl[r1], mu_1 = muv[r1]; int t1 = tok[r1];
        #pragma unroll
        for (int ni = 0; ni < 4; ++ni) {
            int o = wn + ni*8 + (lane & 3)*2;
            float wc0 = swc[o], wc1 = swc[o+1];
            float c00 = sc0[o], c01 = sc0[o+1];
            float* cc = acc[mi][ni];
            decb[(size_t)o*1024 + t0]     = fmaf(sc_0, cc[0] - mu_0*wc0, c00);
            decb[(size_t)(o+1)*1024 + t0] = fmaf(sc_0, cc[1] - mu_0*wc1, c01);
            decb[(size_t)o*1024 + t1]     = fmaf(sc_1, cc[2] - mu_1*wc0, c00);
            decb[(size_t)(o+1)*1024 + t1] = fmaf(sc_1, cc[3] - mu_1*wc1, c01);
        }
    }
}

// =================================================================
extern "C" void kernel_launch(void* const* d_in, const int* in_sizes, int n_in,
                              void* d_out, int out_size)
{
    const float* IF     = (const float*)d_in[0];
    const float* w1     = (const float*)d_in[1];
    const float* b1     = (const float*)d_in[2];
    const float* w2     = (const float*)d_in[3];
    const float* b2     = (const float*)d_in[4];
    const float* wp     = (const float*)d_in[5];
    const float* bp     = (const float*)d_in[6];
    const float* mt     = (const float*)d_in[7];
    const float* conv_w = (const float*)d_in[8];
    const float* conv_b = (const float*)d_in[9];

    float* out = (float*)d_out;
    float* dec = out;                 // 16*256*1024
    float* bin = out + 4194304;       // 16*1*512*512
    float* scm = out + 8388608;       // 16*1*512*512

    const size_t smemX  = (size_t)768*64*sizeof(float);   // 196608
    const size_t smemG1 = 3*65536 + 1024;                 // 197632
    const size_t smemG7 = 2*65536 + 1024;                 // 132096
    cudaFuncSetAttribute(kc_convx, cudaFuncAttributeMaxDynamicSharedMemorySize, (int)smemX);
    cudaFuncSetAttribute(k1g_gemm, cudaFuncAttributeMaxDynamicSharedMemorySize, (int)smemG1);
    cudaFuncSetAttribute(k7g_dec,  cudaFuncAttributeMaxDynamicSharedMemorySize, (int)smemG7);

    // one-time host resources (streams/events, not device memory)
    static cudaStream_t s1 = nullptr, s2 = nullptr, s3 = nullptr;
    static cudaEvent_t  eF = nullptr, eW = nullptr, eS2 = nullptr,
                        eX0 = nullptr, eG0 = nullptr, eK2a = nullptr,
                        eD0 = nullptr, eK2b = nullptr, eK6 = nullptr;
    if (s1 == nullptr) {
        cudaStreamCreateWithFlags(&s1, cudaStreamNonBlocking);
        cudaStreamCreateWithFlags(&s2, cudaStreamNonBlocking);
        cudaStreamCreateWithFlags(&s3, cudaStreamNonBlocking);
        cudaEventCreateWithFlags(&eF,   cudaEventDisableTiming);
        cudaEventCreateWithFlags(&eW,   cudaEventDisableTiming);
        cudaEventCreateWithFlags(&eS2,  cudaEventDisableTiming);
        cudaEventCreateWithFlags(&eX0,  cudaEventDisableTiming);
        cudaEventCreateWithFlags(&eG0,  cudaEventDisableTiming);
        cudaEventCreateWithFlags(&eK2a, cudaEventDisableTiming);
        cudaEventCreateWithFlags(&eD0,  cudaEventDisableTiming);
        cudaEventCreateWithFlags(&eK2b, cudaEventDisableTiming);
        cudaEventCreateWithFlags(&eK6,  cudaEventDisableTiming);
    }

    // fork side streams off the origin (capture) stream
    cudaEventRecord(eF, 0);
    cudaStreamWaitEvent(s1, eF, 0);
    cudaStreamWaitEvent(s2, eF, 0);
    cudaStreamWaitEvent(s3, eF, 0);

    // s1: w1 convert (needed by k1g)
    kc_convw<<<dim3(24, 24), dim3(32, 8), 0, s1>>>(w1);
    cudaEventRecord(eW, s1);

    // s2: side chain for k7g (independent of k1g)
    k3_W<<<dim3(4, 12), 256, 0, s2>>>(wp, conv_w);
    kc_convw2<<<dim3(24, 8), dim3(32, 8), 0, s2>>>();
    kwcol<<<1, 1024, 0, s2>>>();
    k4_c<<<32, 256, 0, s2>>>(conv_w, bp, mt, conv_b);
    k5_fill<<<4096, 256, 0, s2>>>(dec);
    cudaEventRecord(eS2, s2);

    // origin: convert x, half by half (batches 0-7, then 8-15)
    kc_convx<<<128, 512, smemX, 0>>>(IF, 0);
    cudaEventRecord(eX0, 0);
    kc_convx<<<128, 512, smemX, 0>>>(IF, 128);

    // s1: GEMM half 0 (m-tiles 0..63) as soon as convx half 0 done
    // (convw is program-ordered earlier on s1)
    cudaStreamWaitEvent(s1, eX0, 0);
    k1g_gemm<<<384, 512, smemG1, s1>>>(b1, w2, 0);
    cudaEventRecord(eG0, s1);

    // origin: GEMM half 1 (convx half 1 program-ordered; needs weights)
    cudaStreamWaitEvent(0, eW, 0);
    k1g_gemm<<<384, 512, smemG1, 0>>>(b1, w2, 64);

    // s3: batches 0-7 tail concurrent with GEMM half 1
    cudaStreamWaitEvent(s3, eG0, 0);
    k2_topk<<<8, 512, 0, s3>>>(b2, 0);
    cudaEventRecord(eK2a, s3);
    cudaStreamWaitEvent(s3, eS2, 0);
    k7g_dec<<<64, 512, smemG7, s3>>>(dec, 0);
    cudaEventRecord(eD0, s3);

    // origin: batches 8-15 tail
    k2_topk<<<8, 512, 0, 0>>>(b2, 8);
    cudaEventRecord(eK2b, 0);

    // s1: maps need min/max over ALL batches (both k2 halves)
    cudaStreamWaitEvent(s1, eK2a, 0);
    cudaStreamWaitEvent(s1, eK2b, 0);
    k6_maps<<<8192, 512, 0, s1>>>(bin, scm);
    cudaEventRecord(eK6, s1);

    // origin: dec top columns for batches 8-15
    cudaStreamWaitEvent(0, eS2, 0);
    k7g_dec<<<64, 512, smemG7, 0>>>(dec, 64);

    // join all side work back into origin
    cudaStreamWaitEvent(0, eD0, 0);
    cudaStreamWaitEvent(0, eK6, 0);
}

// round 15
// speedup vs baseline: 2.2823x; 1.0026x over previous
#include <cuda_runtime.h>
#include <cuda_bf16.h>
#include <stdint.h>
#include <math.h>

#define BN   16
#define DD   768
#define NN   1024
#define ZZ   256
#define TK   512

// -------- scratch (device globals; no allocation allowed) --------
__device__ float g_score[BN*NN];
__device__ float g_mu[BN*NN];
__device__ float g_rstd[BN*NN];
__device__ int   g_topidx[BN*TK];
__device__ int   g_mask[BN*NN];
__device__ float g_bmin[BN];
__device__ float g_bmax[BN];
__device__ float g_W[DD*ZZ];
__device__ float g_c0[ZZ];
__device__ float g_c1[ZZ];
__device__ float g_wcol[ZZ];
// bf16 split operands + GEMM partials
__device__ __align__(16) __nv_bfloat16 g_xh[16384*768];   // x hi  [token][d]
__device__ __align__(16) __nv_bfloat16 g_xl[16384*768];   // x lo
__device__ __align__(16) __nv_bfloat16 g_wth[768*768];    // w1^T hi [e][k]
__device__ __align__(16) __nv_bfloat16 g_wtl[768*768];    // w1^T lo
__device__ __align__(16) __nv_bfloat16 g_w2h[256*768];    // W^T hi [o][d]
__device__ __align__(16) __nv_bfloat16 g_w2l[256*768];    // W^T lo
__device__ float g_partial[6*16384];                      // per n-tile token partials
__device__ float g_dpart[128*2*16384];                    // k7 split-K partials [tile][kh][o][r]

// ---------------- smem / async helpers ----------------
__device__ __forceinline__ uint32_t smem_u32(const void* p) {
    uint32_t a;
    asm("{ .reg .u64 t; cvta.to.shared.u64 t, %1; cvt.u32.u64 %0, t; }" : "=r"(a) : "l"(p));
    return a;
}
#define SMEM_SWZ(off) ((off) ^ (((off) >> 3) & 0x70))
#define CP16(dst, src)   asm volatile("cp.async.cg.shared.global [%0], [%1], 16;" :: "r"(dst), "l"(src))
#define CP_COMMIT()      asm volatile("cp.async.commit_group;" ::: "memory")
#define CP_WAIT0()       asm volatile("cp.async.wait_group 0;" ::: "memory")
#define CP_WAIT1()       asm volatile("cp.async.wait_group 1;" ::: "memory")

#define LDSM4(r, a) \
    asm volatile("ldmatrix.sync.aligned.m8n8.x4.shared.b16 {%0,%1,%2,%3}, [%4];" \
        : "=r"((r)[0]), "=r"((r)[1]), "=r"((r)[2]), "=r"((r)[3]) : "r"(a))

#define MMA16816(d, a, b0, b1) \
    asm volatile("mma.sync.aligned.m16n8k16.row.col.f32.bf16.bf16.f32 " \
        "{%0,%1,%2,%3},{%4,%5,%6,%7},{%8,%9},{%0,%1,%2,%3};" \
        : "+f"((d)[0]), "+f"((d)[1]), "+f"((d)[2]), "+f"((d)[3]) \
        : "r"((a)[0]), "r"((a)[1]), "r"((a)[2]), "r"((a)[3]), "r"(b0), "r"(b1))

// =================================================================
// KCW: transpose + split w1 -> g_wth/g_wtl [e][k]
// =================================================================
__global__ void kc_convw(const float* __restrict__ w1)
{
    __shared__ float ts[32][33];
    const int tx = threadIdx.x, ty = threadIdx.y;
    const int k0 = blockIdx.x * 32, e0 = blockIdx.y * 32;
    #pragma unroll
    for (int j = 0; j < 32; j += 8)
        ts[ty + j][tx] = w1[(size_t)(k0 + ty + j)*768 + e0 + tx];
    __syncthreads();
    #pragma unroll
    for (int j = 0; j < 32; j += 8) {
        float v = ts[tx][ty + j];
        size_t o = (size_t)(e0 + ty + j)*768 + k0 + tx;
        __nv_bfloat16 h = __float2bfloat16(v);
        g_wth[o] = h;
        g_wtl[o] = __float2bfloat16(v - __bfloat162float(h));
    }
}

// =================================================================
// KCW2: transpose + split g_W[d][o] -> g_w2h/g_w2l [o][d]
// =================================================================
__global__ void kc_convw2()
{
    __shared__ float ts[32][33];
    const int tx = threadIdx.x, ty = threadIdx.y;
    const int d0 = blockIdx.x * 32, o0 = blockIdx.y * 32;
    #pragma unroll
    for (int j = 0; j < 32; j += 8)
        ts[ty + j][tx] = g_W[(size_t)(d0 + ty + j)*256 + o0 + tx];
    __syncthreads();
    #pragma unroll
    for (int j = 0; j < 32; j += 8) {
        float v = ts[tx][ty + j];
        size_t o = (size_t)(o0 + ty + j)*768 + d0 + tx;
        __nv_bfloat16 h = __float2bfloat16(v);
        g_w2h[o] = h;
        g_w2l[o] = __float2bfloat16(v - __bfloat162float(h));
    }
}

// =================================================================
// KWCOL: g_wcol[o] = sum_d W[d][o]  (1024 threads, 4 row-chunks)
// =================================================================
__global__ void kwcol()
{
    __shared__ float red[4][256];
    const int o = threadIdx.x & 255, ch = threadIdx.x >> 8;
    float s = 0.f;
    #pragma unroll 8
    for (int d = ch*192; d < (ch+1)*192; ++d) s += g_W[d*256 + o];
    red[ch][o] = s;
    __syncthreads();
    if (ch == 0) g_wcol[o] = red[0][o] + red[1][o] + red[2][o] + red[3][o];
}

// =================================================================
// KCX: transpose x, compute mu/rstd, split to bf16 hi/lo [token][d]
// =================================================================
__global__ void __launch_bounds__(512, 1)
kc_convx(const float* __restrict__ IF, int blk_base)
{
    extern __shared__ float xs[];          // [d][t] : 768 x 64
    const int tid = threadIdx.x;
    const int ty  = tid >> 5, tx = tid & 31;
    const int blk = blk_base + blockIdx.x;
    const int b   = blk >> 4;
    const int n0  = (blk & 15) << 6;

    const float4* base4 = (const float4*)(IF + (size_t)b * DD * NN);
    const int n04 = n0 >> 2;
    for (int v = tid; v < 64*768/4; v += 512) {
        int d  = v >> 4;
        int t4 = v & 15;
        float4 f = base4[(size_t)d*256 + n04 + t4];
        float2* row = (float2*)(xs + d*64);
        row[t4*2 + 0] = make_float2(f.x, f.y);
        row[t4*2 + 1] = make_float2(f.z, f.w);
    }
    __syncthreads();

    const float2* xs2 = (const float2*)xs;
    for (int i = 0; i < 2; ++i) {
        int tp = ty*2 + i;
        float sx = 0.f, sy = 0.f, ssx = 0.f, ssy = 0.f;
        for (int d = tx; d < 768; d += 32) {
            float2 v = xs2[d*32 + tp];
            sx += v.x; ssx = fmaf(v.x, v.x, ssx);
            sy += v.y; ssy = fmaf(v.y, v.y, ssy);
        }
        for (int off = 16; off; off >>= 1) {
            sx  += __shfl_xor_sync(0xffffffffu, sx,  off);
            sy  += __shfl_xor_sync(0xffffffffu, sy,  off);
            ssx += __shfl_xor_sync(0xffffffffu, ssx, off);
            ssy += __shfl_xor_sync(0xffffffffu, ssy, off);
        }
        if (tx == 0) {
            float mux = sx * (1.0f/768.0f);
            float muy = sy * (1.0f/768.0f);
            g_mu  [b*NN + n0 + 2*tp + 0] = mux;
            g_mu  [b*NN + n0 + 2*tp + 1] = muy;
            g_rstd[b*NN + n0 + 2*tp + 0] = rsqrtf(ssx*(1.0f/768.0f) - mux*mux + 1e-5f);
            g_rstd[b*NN + n0 + 2*tp + 1] = rsqrtf(ssy*(1.0f/768.0f) - muy*muy + 1e-5f);
        }
    }

    const int t  = tid & 63, dq = tid >> 6;
    const int gtok = b*1024 + n0 + t;
    uint4* oh = (uint4*)(g_xh + (size_t)gtok*768);
    uint4* ol = (uint4*)(g_xl + (size_t)gtok*768);
    for (int d8 = dq; d8 < 96; d8 += 8) {
        union { __nv_bfloat16 h[8]; uint4 u; } Uh, Ul;
        #pragma unroll
        for (int i = 0; i < 8; ++i) {
            float v = xs[(d8*8 + i)*64 + t];
            __nv_bfloat16 h = __float2bfloat16(v);
            Uh.h[i] = h;
            Ul.h[i] = __float2bfloat16(v - __bfloat162float(h));
        }
        oh[d8] = Uh.u;
        ol[d8] = Ul.u;
    }
}

// =================================================================
// K1G: HMMA split GEMM: 512 threads, 16 warps (4m x 4n),
// warp 32x32, BK=64, 3-stage / 1 barrier per chunk.
// =================================================================
__global__ void __launch_bounds__(512, 1)
k1g_gemm(const float* __restrict__ b1, const float* __restrict__ w2, int m_base)
{
    extern __shared__ char dsm[];
    __shared__ float sb1[128];
    __shared__ float sw2[128];
    __shared__ float spart[128];

    const int tid  = threadIdx.x;
    const int wid  = tid >> 5, lane = tid & 31;
    const int mt   = m_base + blockIdx.x / 6;
    const int nt   = blockIdx.x % 6;
    const int m0   = mt * 128;
    const int e0   = nt * 128;
    const int wm   = (wid & 3) * 32;
    const int wn   = (wid >> 2) * 32;

    const uint32_t sbase = (smem_u32(dsm) + 1023u) & ~1023u;

    if (tid < 128) {
        sb1[tid]   = b1[e0 + tid];
        sw2[tid]   = w2[e0 + tid];
        spart[tid] = 0.f;
    }

    const char* xh = (const char*)g_xh;
    const char* xl = (const char*)g_xl;
    const char* wh = (const char*)g_wth;
    const char* wl = (const char*)g_wtl;

    auto load_chunk = [&](int c, int st) {
        const uint32_t sA = sbase + (uint32_t)st * 65536u;
        const int kb = c * 128;
        #pragma unroll
        for (int q = 0; q < 4; ++q) {
            int idx  = tid + q*512;
            int half = idx >> 10, rem = idx & 1023;
            int r = rem >> 3, ci = rem & 7;
            uint32_t off = (uint32_t)(r*128 + ci*16);
            uint32_t dst = sA + (uint32_t)half*16384u + SMEM_SWZ(off);
            const char* src = (half ? xl : xh) + (size_t)(m0 + r)*1536 + kb + ci*16;
            CP16(dst, src);
        }
        #pragma unroll
        for (int q = 0; q < 4; ++q) {
            int idx  = tid + q*512;
            int half = idx >> 10, rem = idx & 1023;
            int r = rem >> 3, ci = rem & 7;
            uint32_t off = (uint32_t)(r*128 + ci*16);
            uint32_t dst = sA + 32768u + (uint32_t)half*16384u + SMEM_SWZ(off);
            const char* src = (half ? wl : wh) + (size_t)(e0 + r)*1536 + kb + ci*16;
            CP16(dst, src);
        }
        CP_COMMIT();
    };

    float acc[2][4][4];
    #pragma unroll
    for (int i = 0; i < 2; ++i)
        #pragma unroll
        for (int j = 0; j < 4; ++j)
            #pragma unroll
            for (int q = 0; q < 4; ++q) acc[i][j][q] = 0.f;

    load_chunk(0, 0);
    load_chunk(1, 1);

    const int arow  = lane & 15;
    const int akoff = (lane >> 4) * 16;

    int stage = 0;
    for (int c = 0; c < 12; ++c) {
        if (c < 11) CP_WAIT1(); else CP_WAIT0();
        __syncthreads();
        if (c + 2 < 12) {
            int s2 = stage + 2; if (s2 >= 3) s2 -= 3;
            load_chunk(c + 2, s2);
        }

        const uint32_t sA = sbase + (uint32_t)stage * 65536u;
        #pragma unroll
        for (int ks = 0; ks < 4; ++ks) {
            const int kbyte = ks*32;
            uint32_t ah[2][4], al[2][4], bh[2][4], bl[2][4];
            #pragma unroll
            for (int mi = 0; mi < 2; ++mi) {
                uint32_t off = (uint32_t)((wm + mi*16 + arow)*128 + kbyte + akoff);
                uint32_t ad  = sA + SMEM_SWZ(off);
                LDSM4(ah[mi], ad);
                LDSM4(al[mi], ad + 16384u);
            }
            #pragma unroll
            for (int bi = 0; bi < 2; ++bi) {
                uint32_t off = (uint32_t)((wn + bi*16 + arow)*128 + kbyte + akoff);
                uint32_t bd  = sA + 32768u + SMEM_SWZ(off);
                LDSM4(bh[bi], bd);
                LDSM4(bl[bi], bd + 16384u);
            }
            #pragma unroll
            for (int mi = 0; mi < 2; ++mi)
                #pragma unroll
                for (int ni = 0; ni < 4; ++ni) {
                    const int bi = ni >> 1, s = ni & 1;
                    MMA16816(acc[mi][ni], ah[mi], bh[bi][s], bh[bi][s + 2]);
                }
            #pragma unroll
            for (int mi = 0; mi < 2; ++mi)
                #pragma unroll
                for (int ni = 0; ni < 4; ++ni) {
                    const int bi = ni >> 1, s = ni & 1;
                    MMA16816(acc[mi][ni], al[mi], bh[bi][s], bh[bi][s + 2]);
                }
            #pragma unroll
            for (int mi = 0; mi < 2; ++mi)
                #pragma unroll
                for (int ni = 0; ni < 4; ++ni) {
                    const int bi = ni >> 1, s = ni & 1;
                    MMA16816(acc[mi][ni], ah[mi], bl[bi][s], bl[bi][s + 2]);
                }
        }
        if (++stage >= 3) stage = 0;
    }

    #pragma unroll
    for (int mi = 0; mi < 2; ++mi) {
        float s0 = 0.f, s1 = 0.f;
        #pragma unroll
        for (int ni = 0; ni < 4; ++ni) {
            int e  = wn + ni*8 + (lane & 3)*2;
            float b0 = sb1[e], b1v = sb1[e+1];
            float w0 = sw2[e], w1v = sw2[e+1];
            float* cc = acc[mi][ni];
            s0 = fmaf(fmaxf(cc[0] + b0, 0.f), w0, s0);
            s0 = fmaf(fmaxf(cc[1] + b1v, 0.f), w1v, s0);
            s1 = fmaf(fmaxf(cc[2] + b0, 0.f), w0, s1);
            s1 = fmaf(fmaxf(cc[3] + b1v, 0.f), w1v, s1);
        }
        s0 += __shfl_xor_sync(0xffffffffu, s0, 1);
        s0 += __shfl_xor_sync(0xffffffffu, s0, 2);
        s1 += __shfl_xor_sync(0xffffffffu, s1, 1);
        s1 += __shfl_xor_sync(0xffffffffu, s1, 2);
        if ((lane & 3) == 0) {
            int r = wm + mi*16 + (lane >> 2);
            atomicAdd(&spart[r], s0);
            atomicAdd(&spart[r + 8], s1);
        }
    }
    __syncthreads();
    if (tid < 128) g_partial[nt*16384 + m0 + tid] = spart[tid];
}

// =================================================================
// K2: sum partials -> sigmoid -> score; per-batch top-512 bitonic.
// =================================================================
__global__ void k2_topk(const float* __restrict__ b2, int b_base)
{
    __shared__ unsigned long long keys[1024];
    __shared__ int msk[1024];
    __shared__ int pA[1024];
    __shared__ int pB[1024];
    const int b = b_base + blockIdx.x, tid = threadIdx.x;
    const float b2v = b2[0];

    for (int i = tid; i < 1024; i += 512) {
        int gt = b*NN + i;
        float pre = b2v;
        #pragma unroll
        for (int q = 0; q < 6; ++q) pre += g_partial[q*16384 + gt];
        float sc = 1.0f / (1.0f + expf(-pre));
        g_score[gt] = sc;
        unsigned u = __float_as_uint(sc);
        u = (u & 0x80000000u) ? ~u : (u | 0x80000000u);
        keys[i] = ((unsigned long long)u << 32) | (unsigned)(1023 - i);
    }
    __syncthreads();

    for (int k = 2; k <= 1024; k <<= 1)
        for (int j = k >> 1; j > 0; j >>= 1) {
            for (int i = tid; i < 1024; i += 512) {
                int ixj = i ^ j;
                if (ixj > i) {
                    bool up = ((i & k) == 0);
                    unsigned long long a = keys[i], c = keys[ixj];
                    if ((a > c) == up) { keys[i] = c; keys[ixj] = a; }
                }
            }
            __syncthreads();
        }

    for (int i = tid; i < 1024; i += 512) {
        int n = 1023 - (int)(unsigned)(keys[i] & 0xffffffffull);
        msk[n] = (i >= 512) ? 1 : 0;
    }
    __syncthreads();
    for (int i = tid; i < 1024; i += 512) { g_mask[b*NN + i] = msk[i]; pA[i] = msk[i]; }
    __syncthreads();

    int* src = pA; int* dst = pB;
    for (int off = 1; off < 1024; off <<= 1) {
        for (int i = tid; i < 1024; i += 512)
            dst[i] = src[i] + ((i >= off) ? src[i - off] : 0);
        __syncthreads();
        int* t = src; src = dst; dst = t;
    }
    for (int i = tid; i < 1024; i += 512)
        if (msk[i]) g_topidx[b*TK + src[i] - 1] = i;

    if (tid == 0) {
        unsigned umax = (unsigned)(keys[1023] >> 32);
        unsigned umin = (unsigned)(keys[0]    >> 32);
        g_bmax[b] = (umax & 0x80000000u) ? __uint_as_float(umax ^ 0x80000000u)
                                         : __uint_as_float(~umax);
        g_bmin[b] = (umin & 0x80000000u) ? __uint_as_float(umin ^ 0x80000000u)
                                         : __uint_as_float(~umin);
    }
}

// =================================================================
// K3: W = wp @ conv_w^T  (768x256 · 256x256), tiled 64x64.
// =================================================================
__global__ void k3_W(const float* __restrict__ wp, const float* __restrict__ conv_w)
{
    __shared__ float As[32*68];
    __shared__ float Bs[32*68];
    const int tid = threadIdx.x;
    const int tx  = tid & 15, ty = tid >> 4;
    const int o0  = blockIdx.x * 64;
    const int d0  = blockIdx.y * 64;

    float acc[4][4];
    #pragma unroll
    for (int i = 0; i < 4; ++i)
        #pragma unroll
        for (int j = 0; j < 4; ++j) acc[i][j] = 0.f;

    for (int k0 = 0; k0 < 256; k0 += 32) {
        #pragma unroll
        for (int q = 0; q < 8; ++q) {
            int v = tid + q*256;
            int r = v >> 5, kk = v & 31;
            As[kk*68 + r] = wp    [(size_t)(d0 + r)*256 + k0 + kk];
            Bs[kk*68 + r] = conv_w[(size_t)(o0 + r)*256 + k0 + kk];
        }
        __syncthreads();
        #pragma unroll
        for (int kk = 0; kk < 32; ++kk) {
            float a[4], bb[4];
            #pragma unroll
            for (int i = 0; i < 4; ++i) a[i]  = As[kk*68 + ty*4 + i];
            #pragma unroll
            for (int j = 0; j < 4; ++j) bb[j] = Bs[kk*68 + tx*4 + j];
            #pragma unroll
            for (int i = 0; i < 4; ++i)
                #pragma unroll
                for (int j = 0; j < 4; ++j)
                    acc[i][j] = fmaf(a[i], bb[j], acc[i][j]);
        }
        __syncthreads();
    }
    #pragma unroll
    for (int i = 0; i < 4; ++i)
        #pragma unroll
        for (int j = 0; j < 4; ++j)
            g_W[(size_t)(d0 + ty*4 + i)*256 + o0 + tx*4 + j] = acc[i][j];
}

// =================================================================
// K4: c0/c1 bias vectors (one warp per output o)
// =================================================================
__global__ void k4_c(const float* __restrict__ conv_w, const float* __restrict__ bp,
                     const float* __restrict__ mt, const float* __restrict__ conv_b)
{
    const int o    = blockIdx.x * 8 + (threadIdx.x >> 5);
    const int lane = threadIdx.x & 31;
    float s0 = 0.f, s1 = 0.f;
    #pragma unroll
    for (int z = lane; z < 256; z += 32) {
        float cw = conv_w[o*256 + z];
        s0 = fmaf(cw, bp[z], s0);
        s1 = fmaf(cw, mt[z], s1);
    }
    for (int off = 16; off; off >>= 1) {
        s0 += __shfl_xor_sync(0xffffffffu, s0, off);
        s1 += __shfl_xor_sync(0xffffffffu, s1, off);
    }
    if (lane == 0) {
        g_c0[o] = s0 + conv_b[o];
        g_c1[o] = s1 + conv_b[o];
    }
}

// =================================================================
// K5: fill dec with constant non-top column c1
// =================================================================
__global__ void k5_fill(float* __restrict__ dec)
{
    int b = blockIdx.x >> 8, o = blockIdx.x & 255;
    float c = g_c1[o];
    float4 f = make_float4(c, c, c, c);
    float4* row = (float4*)(dec + ((size_t)b*256 + o)*1024);
    row[threadIdx.x] = f;
}

// =================================================================
// K6: binary_map + score_map (needs ALL batches' min/max)
// =================================================================
__global__ void k6_maps(float* __restrict__ bin, float* __restrict__ scm)
{
    const int b = blockIdx.x >> 9;
    const int y = blockIdx.x & 511;
    float mn = g_bmin[0], mx = g_bmax[0];
    #pragma unroll
    for (int k = 1; k < 16; ++k) { mn = fminf(mn, g_bmin[k]); mx = fmaxf(mx, g_bmax[k]); }
    float inv = 1.0f / fmaxf(mx - mn, 1e-5f);

    const int x = threadIdx.x;
    const int n = (y >> 4)*32 + (x >> 4);
    size_t o = (size_t)b*262144 + (size_t)y*512 + x;
    bin[o] = g_mask[b*NN + n] ? 1.0f : 0.0f;
    scm[o] = (g_score[b*NN + n] - mn) * inv;
}

// =================================================================
// K7S: split-K HMMA raw GEMM for dec top columns (validated in R12).
// 2 CTAs per tile (K halves of 6 chunks); raw fp32 accum to g_dpart
// in [tile][kh][o][r] layout.  tile = b*8 + st*2 + nt (128 tiles).
// =================================================================
__global__ void __launch_bounds__(512, 1)
k7s_gemm(int tile_base)
{
    extern __shared__ char dsm[];
    __shared__ int tok[128];

    const int tid  = threadIdx.x;
    const int wid  = tid >> 5, lane = tid & 31;
    const int tile = tile_base + (blockIdx.x >> 1);
    const int kh   = blockIdx.x & 1;
    const int b    = tile >> 3;
    const int st   = (tile >> 1) & 3;
    const int nt   = tile & 1;
    const int s0   = st * 128;
    const int o0   = nt * 128;
    const int wm   = (wid & 3) * 32;
    const int wn   = (wid >> 2) * 32;

    const uint32_t sbase = (smem_u32(dsm) + 1023u) & ~1023u;

    if (tid < 128) tok[tid] = g_topidx[b*TK + s0 + tid];
    __syncthreads();

    const char* xh = (const char*)g_xh;
    const char* xl = (const char*)g_xl;
    const char* wh = (const char*)g_w2h;
    const char* wl = (const char*)g_w2l;
    const int kc0 = kh * 6;

    auto load_chunk = [&](int c, int stg) {
        const uint32_t sA = sbase + (uint32_t)stg * 65536u;
        const int kb = (kc0 + c) * 128;
        #pragma unroll
        for (int q = 0; q < 4; ++q) {
            int idx  = tid + q*512;
            int half = idx >> 10, rem = idx & 1023;
            int r = rem >> 3, ci = rem & 7;
            uint32_t off = (uint32_t)(r*128 + ci*16);
            uint32_t dst = sA + (uint32_t)half*16384u + SMEM_SWZ(off);
            size_t grow = (size_t)(b*1024 + tok[r]);
            const char* src = (half ? xl : xh) + grow*1536 + kb + ci*16;
            CP16(dst, src);
        }
        #pragma unroll
        for (int q = 0; q < 4; ++q) {
            int idx  = tid + q*512;
            int half = idx >> 10, rem = idx & 1023;
            int r = rem >> 3, ci = rem & 7;
            uint32_t off = (uint32_t)(r*128 + ci*16);
            uint32_t dst = sA + 32768u + (uint32_t)half*16384u + SMEM_SWZ(off);
            const char* src = (half ? wl : wh) + (size_t)(o0 + r)*1536 + kb + ci*16;
            CP16(dst, src);
        }
        CP_COMMIT();
    };

    float acc[2][4][4];
    #pragma unroll
    for (int i = 0; i < 2; ++i)
        #pragma unroll
        for (int j = 0; j < 4; ++j)
            #pragma unroll
            for (int q = 0; q < 4; ++q) acc[i][j][q] = 0.f;

    load_chunk(0, 0);

    const int arow  = lane & 15;
    const int akoff = (lane >> 4) * 16;

    for (int c = 0; c < 6; ++c) {
        if (c + 1 < 6) { load_chunk(c + 1, (c + 1) & 1); CP_WAIT1(); }
        else           { CP_WAIT0(); }
        __syncthreads();

        const uint32_t sA = sbase + (uint32_t)(c & 1) * 65536u;
        #pragma unroll
        for (int ks = 0; ks < 4; ++ks) {
            const int kbyte = ks*32;
            uint32_t ah[2][4], al[2][4], bh[2][4], bl[2][4];
            #pragma unroll
            for (int mi = 0; mi < 2; ++mi) {
                uint32_t off = (uint32_t)((wm + mi*16 + arow)*128 + kbyte + akoff);
                uint32_t ad  = sA + SMEM_SWZ(off);
                LDSM4(ah[mi], ad);
                LDSM4(al[mi], ad + 16384u);
            }
            #pragma unroll
            for (int bi = 0; bi < 2; ++bi) {
                uint32_t off = (uint32_t)((wn + bi*16 + arow)*128 + kbyte + akoff);
                uint32_t bd  = sA + 32768u + SMEM_SWZ(off);
                LDSM4(bh[bi], bd);
                LDSM4(bl[bi], bd + 16384u);
            }
            #pragma unroll
            for (int mi = 0; mi < 2; ++mi)
                #pragma unroll
                for (int ni = 0; ni < 4; ++ni) {
                    const int bi = ni >> 1, s = ni & 1;
                    MMA16816(acc[mi][ni], ah[mi], bh[bi][s], bh[bi][s + 2]);
                }
            #pragma unroll
            for (int mi = 0; mi < 2; ++mi)
                #pragma unroll
                for (int ni = 0; ni < 4; ++ni) {
                    const int bi = ni >> 1, s = ni & 1;
                    MMA16816(acc[mi][ni], al[mi], bh[bi][s], bh[bi][s + 2]);
                }
            #pragma unroll
            for (int mi = 0; mi < 2; ++mi)
                #pragma unroll
                for (int ni = 0; ni < 4; ++ni) {
                    const int bi = ni >> 1, s = ni & 1;
                    MMA16816(acc[mi][ni], ah[mi], bl[bi][s], bl[bi][s + 2]);
                }
        }
        __syncthreads();
    }

    float* dp = g_dpart + ((size_t)tile*2 + kh)*16384;
    #pragma unroll
    for (int mi = 0; mi < 2; ++mi) {
        int r0 = wm + mi*16 + (lane >> 2);
        int r1 = r0 + 8;
        #pragma unroll
        for (int ni = 0; ni < 4; ++ni) {
            int o = wn + ni*8 + (lane & 3)*2;
            float* cc = acc[mi][ni];
            dp[o*128 + r0]       = cc[0];
            dp[(o+1)*128 + r0]   = cc[1];
            dp[o*128 + r1]       = cc[2];
            dp[(o+1)*128 + r1]   = cc[3];
        }
    }
}

// =================================================================
// K7C: combine split-K partials -> dec (deterministic p0+p1).
// =================================================================
__global__ void k7_combine(float* __restrict__ dec, int tile_base)
{
    __shared__ int   tok[128];
    __shared__ float scl[128];
    __shared__ float muv[128];
    __shared__ float swc[128];
    __shared__ float sc0[128];

    const int tile = tile_base + blockIdx.x;
    const int b  = tile >> 3;
    const int st = (tile >> 1) & 3;
    const int nt = tile & 1;
    const int s0 = st * 128;
    const int o0 = nt * 128;
    const int tid = threadIdx.x;   // 256

    if (tid < 128) {
        int t = g_topidx[b*TK + s0 + tid];
        tok[tid] = t;
        muv[tid] = g_mu[b*NN + t];
        scl[tid] = g_rstd[b*NN + t] * g_score[b*NN + t];
        swc[tid] = g_wcol[o0 + tid];
        sc0[tid] = g_c0[o0 + tid];
    }
    __syncthreads();

    const float* p0 = g_dpart + ((size_t)tile*2 + 0)*16384;
    const float* p1 = g_dpart + ((size_t)tile*2 + 1)*16384;
    float* decb = dec + (size_t)(b*256 + o0)*1024;

    for (int i = tid; i < 16384; i += 256) {
        int o = i >> 7, r = i & 127;
        float v = p0[i] + p1[i];
        decb[(size_t)o*1024 + tok[r]] = fmaf(scl[r], v - muv[r]*swc[o], sc0[o]);
    }
}

// =================================================================
extern "C" void kernel_launch(void* const* d_in, const int* in_sizes, int n_in,
                              void* d_out, int out_size)
{
    const float* IF     = (const float*)d_in[0];
    const float* w1     = (const float*)d_in[1];
    const float* b1     = (const float*)d_in[2];
    const float* w2     = (const float*)d_in[3];
    const float* b2     = (const float*)d_in[4];
    const float* wp     = (const float*)d_in[5];
    const float* bp     = (const float*)d_in[6];
    const float* mt     = (const float*)d_in[7];
    const float* conv_w = (const float*)d_in[8];
    const float* conv_b = (const float*)d_in[9];

    float* out = (float*)d_out;
    float* dec = out;                 // 16*256*1024
    float* bin = out + 4194304;       // 16*1*512*512
    float* scm = out + 8388608;       // 16*1*512*512

    const size_t smemX  = (size_t)768*64*sizeof(float);   // 196608
    const size_t smemG1 = 3*65536 + 1024;                 // 197632
    const size_t smemG7 = 2*65536 + 1024;                 // 132096
    cudaFuncSetAttribute(kc_convx, cudaFuncAttributeMaxDynamicSharedMemorySize, (int)smemX);
    cudaFuncSetAttribute(k1g_gemm, cudaFuncAttributeMaxDynamicSharedMemorySize, (int)smemG1);
    cudaFuncSetAttribute(k7s_gemm, cudaFuncAttributeMaxDynamicSharedMemorySize, (int)smemG7);

    // one-time host resources (streams/events, not device memory)
    static cudaStream_t s1 = nullptr, s2 = nullptr, s3 = nullptr;
    static cudaEvent_t  eF = nullptr, eW = nullptr, eS2 = nullptr,
                        eX0 = nullptr, eG0 = nullptr, eK2a = nullptr,
                        eD0 = nullptr, eK2b = nullptr, eK6 = nullptr;
    if (s1 == nullptr) {
        cudaStreamCreateWithFlags(&s1, cudaStreamNonBlocking);
        cudaStreamCreateWithFlags(&s2, cudaStreamNonBlocking);
        cudaStreamCreateWithFlags(&s3, cudaStreamNonBlocking);
        cudaEventCreateWithFlags(&eF,   cudaEventDisableTiming);
        cudaEventCreateWithFlags(&eW,   cudaEventDisableTiming);
        cudaEventCreateWithFlags(&eS2,  cudaEventDisableTiming);
        cudaEventCreateWithFlags(&eX0,  cudaEventDisableTiming);
        cudaEventCreateWithFlags(&eG0,  cudaEventDisableTiming);
        cudaEventCreateWithFlags(&eK2a, cudaEventDisableTiming);
        cudaEventCreateWithFlags(&eD0,  cudaEventDisableTiming);
        cudaEventCreateWithFlags(&eK2b, cudaEventDisableTiming);
        cudaEventCreateWithFlags(&eK6,  cudaEventDisableTiming);
    }

    // fork side streams off the origin (capture) stream
    cudaEventRecord(eF, 0);
    cudaStreamWaitEvent(s1, eF, 0);
    cudaStreamWaitEvent(s2, eF, 0);
    cudaStreamWaitEvent(s3, eF, 0);

    // s1: w1 convert (needed by k1g)
    kc_convw<<<dim3(24, 24), dim3(32, 8), 0, s1>>>(w1);
    cudaEventRecord(eW, s1);

    // s2: side chain for k7 (independent of k1g)
    k3_W<<<dim3(4, 12), 256, 0, s2>>>(wp, conv_w);
    kc_convw2<<<dim3(24, 8), dim3(32, 8), 0, s2>>>();
    kwcol<<<1, 1024, 0, s2>>>();
    k4_c<<<32, 256, 0, s2>>>(conv_w, bp, mt, conv_b);
    k5_fill<<<4096, 256, 0, s2>>>(dec);
    cudaEventRecord(eS2, s2);

    // origin: convert x, half by half (batches 0-7, then 8-15)
    kc_convx<<<128, 512, smemX, 0>>>(IF, 0);
    cudaEventRecord(eX0, 0);
    kc_convx<<<128, 512, smemX, 0>>>(IF, 128);

    // s1: GEMM half 0 (m-tiles 0..63) as soon as convx half 0 done
    cudaStreamWaitEvent(s1, eX0, 0);
    k1g_gemm<<<384, 512, smemG1, s1>>>(b1, w2, 0);
    cudaEventRecord(eG0, s1);

    // origin: GEMM half 1 (convx half 1 program-ordered; needs weights)
    cudaStreamWaitEvent(0, eW, 0);
    k1g_gemm<<<384, 512, smemG1, 0>>>(b1, w2, 64);

    // s3: batches 0-7 tail concurrent with GEMM half 1 (split-K dec)
    cudaStreamWaitEvent(s3, eG0, 0);
    k2_topk<<<8, 512, 0, s3>>>(b2, 0);
    cudaEventRecord(eK2a, s3);
    cudaStreamWaitEvent(s3, eS2, 0);
    k7s_gemm<<<128, 512, smemG7, s3>>>(0);          // tiles 0-63, both K halves
    k7_combine<<<64, 256, 0, s3>>>(dec, 0);
    cudaEventRecord(eD0, s3);

    // origin: batches 8-15 tail
    k2_topk<<<8, 512, 0, 0>>>(b2, 8);
    cudaEventRecord(eK2b, 0);

    // s1: maps need min/max over ALL batches (both k2 halves)
    cudaStreamWaitEvent(s1, eK2a, 0);
    cudaStreamWaitEvent(s1, eK2b, 0);
    k6_maps<<<8192, 512, 0, s1>>>(bin, scm);
    cudaEventRecord(eK6, s1);

    // origin: dec top columns for batches 8-15 (split-K: half CTA duration)
    cudaStreamWaitEvent(0, eS2, 0);
    k7s_gemm<<<128, 512, smemG7, 0>>>(64);          // tiles 64-127
    k7_combine<<<64, 256, 0, 0>>>(dec, 64);

    // join all side work back into origin
    cudaStreamWaitEvent(0, eD0, 0);
    cudaStreamWaitEvent(0, eK6, 0);
}